// round 12
// baseline (speedup 1.0000x reference)
#include <cuda_runtime.h>
#include <cuda_bf16.h>
#include <cstdint>

// Problem constants
#define B_   128
#define L_   512
#define W_   256
#define CN_  4
#define G_   4
#define Lp_  508            // L - KH + 1
#define NB_  65024          // B_*Lp_ = 508*128 exactly
#define LBL_ 53
#define EPSF 1e-5f
#define NEGF (-100000.0f)
#define FNEG (-3.0e38f)
#define GCNT 32512.0f       // 64 * Lp_

#define HROW 68             // b32 per l row of h (136 bf16: 130 data + 6 pad)
#define K1PW 352            // b32 k-pairs per conv1 weight row (704 bf16)
#define C1_NIT 11           // 352/32 b32 (k64 bf16 per stage)
#define CB_NIT 32           // 32 k32-steps (4 tiles x 8)
#define NCH 8               // l-chunks for partial max

// Scratch (static device memory -- no allocations allowed)
__device__ uint32_t g_hb[(size_t)B_ * L_ * HROW + 4096]; // bf16-pair h, [b*L+l][68]
__device__ uint32_t g_w1h[(size_t)W_ * K1PW];            // conv1 w [w][352]
__device__ uint32_t g_cbwh[(size_t)CN_ * W_ * 128];      // cb w, bf16 [i][256][128 b32]
__device__ uint32_t g_yh[(size_t)NB_ * 128];             // y bf16 pairs [nb][128 b32]
__device__ uint32_t g_xIh[(size_t)NB_ * 128];            // xI bf16 pairs [nb][128 b32]
__device__ uint32_t g_zh[(size_t)NB_ * 128];             // z bf16 pairs [nb][128 b32]
__device__ float    g_psum2[CN_ * B_ * G_ * 2];          // per-layer (sum, sumsq)
__device__ float    g_pmax[B_ * NCH * 3 * W_];

// ---------------------------------------------------------------------------
// helpers
// ---------------------------------------------------------------------------
__device__ __forceinline__ uint32_t cvta_s(const void* p) {
    return (uint32_t)__cvta_generic_to_shared(p);
}
__device__ __forceinline__ void cp16(uint32_t s, const void* g) {
    asm volatile("cp.async.cg.shared.global [%0],[%1],16;" :: "r"(s), "l"(g));
}
#define CP_COMMIT() asm volatile("cp.async.commit_group;")
#define CP_WAIT1()  asm volatile("cp.async.wait_group 1;")
#define CP_WAIT0()  asm volatile("cp.async.wait_group 0;")

__device__ __forceinline__ void ldm4(uint32_t* r, uint32_t addr) {
    asm volatile("ldmatrix.sync.aligned.m8n8.x4.shared.b16 {%0,%1,%2,%3}, [%4];"
        : "=r"(r[0]), "=r"(r[1]), "=r"(r[2]), "=r"(r[3]) : "r"(addr));
}

__device__ __forceinline__ void mma16(float* c, const uint32_t* a,
                                      uint32_t b0, uint32_t b1) {
    asm volatile(
        "mma.sync.aligned.m16n8k16.row.col.f32.bf16.bf16.f32 "
        "{%0,%1,%2,%3}, {%4,%5,%6,%7}, {%8,%9}, {%0,%1,%2,%3};"
        : "+f"(c[0]), "+f"(c[1]), "+f"(c[2]), "+f"(c[3])
        : "r"(a[0]), "r"(a[1]), "r"(a[2]), "r"(a[3]), "r"(b0), "r"(b1));
}

__device__ __forceinline__ uint32_t packbf(float lo, float hi) {
    __nv_bfloat162 t = __floats2bfloat162_rn(lo, hi);
    return *(uint32_t*)&t;
}
__device__ __forceinline__ float bf_lo(uint32_t u) {
    __nv_bfloat162 t = *(__nv_bfloat162*)&u;
    return __bfloat162float(t.x);
}
__device__ __forceinline__ float bf_hi(uint32_t u) {
    __nv_bfloat162 t = *(__nv_bfloat162*)&u;
    return __bfloat162float(t.y);
}
__device__ __forceinline__ float2 gn_stats(int blk, int b, int g) {
    const float* ps = g_psum2 + ((blk * B_ + b) * G_ + g) * 2;
    float s = __ldg(ps), q = __ldg(ps + 1);
    float mean = s / GCNT;
    float var  = q / GCNT - mean * mean;
    return make_float2(mean, rsqrtf(var + EPSF));
}

// ---------------------------------------------------------------------------
// 0a) conv1 weight prep: [w][650] fp32 -> [w][352] bf16-pair (window layout)
// ---------------------------------------------------------------------------
__global__ void prep_w1h(const float* __restrict__ w)
{
    int idx = blockIdx.x * 256 + threadIdx.x;
    if (idx >= W_ * K1PW) return;
    int m = idx / K1PW, kp = idx - m * K1PW;
    int ks = 2 * kp;
    float v0 = 0.f, v1 = 0.f;
    int seg0 = ks / 136, off0 = ks - seg0 * 136;
    if (seg0 < 5 && off0 < 130)     v0 = w[m * 650 + seg0 * 130 + off0];
    int ks1 = ks + 1;
    int seg1 = ks1 / 136, off1 = ks1 - seg1 * 136;
    if (seg1 < 5 && off1 < 130)     v1 = w[m * 650 + seg1 * 130 + off1];
    g_w1h[idx] = packbf(v0, v1);
}

// ---------------------------------------------------------------------------
// 0b) cb weight prep + per-layer psum zero init (once)
// ---------------------------------------------------------------------------
__global__ void prep_cbwh(const float* __restrict__ w)
{
    int idx = blockIdx.x * 256 + threadIdx.x;
    if (idx < CN_ * B_ * G_ * 2) g_psum2[idx] = 0.f;
    if (idx >= CN_ * W_ * 128) return;
    int row = idx >> 7;
    int kp  = idx & 127;
    const float* src = w + (size_t)row * W_ + 2 * kp;
    g_cbwh[idx] = packbf(src[0], src[1]);
}

// ---------------------------------------------------------------------------
// 1) embedding + position -> g_hb bf16 pairs [b*L+l][68]; zeros pad + tail
// ---------------------------------------------------------------------------
__global__ void embed_h(const int* __restrict__ x,
                        const float* __restrict__ pe,
                        const float* __restrict__ emb)
{
    int id = blockIdx.x * 256 + threadIdx.x;
    const int MAIN = B_ * L_ * HROW;
    if (id >= MAIN + 4096) return;
    if (id >= MAIN) { g_hb[id] = 0u; return; }
    int bl = id / HROW, t = id - bl * HROW;
    float v0 = 0.f, v1 = 0.f;
    if (t < 64) {
        int tok = x[bl];
        const float* e = emb + (size_t)tok * 128 + 2 * t;
        v0 = e[0]; v1 = e[1];
    } else if (t == 64) {
        v0 = pe[bl * 2]; v1 = pe[bl * 2 + 1];
    }
    g_hb[id] = packbf(v0, v1);
}

// ---------------------------------------------------------------------------
// 2) conv1: C[n][w] = window(h)[n][704] @ w1[w][704]^T, per-batch.
//    k64 stages (11 iterations), 3-stage ring. Row pitch 144 B.
//    smem: 3 * (18432 + 18432) = 110592 B.
// ---------------------------------------------------------------------------
__global__ __launch_bounds__(256, 2) void conv1_tc(
    const float* __restrict__ bias,
    const float* __restrict__ bg, const float* __restrict__ bb,
    const float* __restrict__ bmu, const float* __restrict__ bvv,
    const float* __restrict__ pw)
{
    extern __shared__ uint32_t sm[];
    uint32_t sb = cvta_s(sm);
    const uint32_t WREG = sb + 55296;       // W region base
    int b  = blockIdx.z;
    int m0 = blockIdx.y * 128;     // n-position tile
    int n0 = blockIdx.x * 128;     // w tile
    int t = threadIdx.x, lane = t & 31, wid = t >> 5;
    int wm = wid >> 2, wn = wid & 3;
    int fr = lane >> 2, fc = lane & 3;

    float acc[4][4][4];
    #pragma unroll
    for (int i = 0; i < 4; i++)
        #pragma unroll
        for (int j = 0; j < 4; j++)
            #pragma unroll
            for (int q = 0; q < 4; q++) acc[i][j][q] = 0.f;

    int lr = t >> 1, seg = t & 1;
    const uint32_t* agp = g_hb + (size_t)(b * 512 + m0 + lr) * HROW + seg * 16;
    const uint32_t* wgp = g_w1h + (size_t)(n0 + lr) * K1PW + seg * 16;
    uint32_t aS = sb + lr * 144 + seg * 64;
    uint32_t wS = WREG + lr * 144 + seg * 64;

    uint32_t aAddr[4];
    #pragma unroll
    for (int i = 0; i < 4; i++) {
        int row = wm * 64 + 16 * i + (lane & 15);
        aAddr[i] = sb + row * 144 + ((lane & 16) ? 16 : 0);
    }
    uint32_t bAddr = WREG + (wn * 32 + lane) * 144;

    #define C1_ISSUE(it_) do { \
        uint32_t so_ = ((it_) % 3) * 18432; \
        _Pragma("unroll") \
        for (int q_ = 0; q_ < 4; q_++) { \
            cp16(aS + so_ + q_ * 16, agp + (it_) * 32 + q_ * 4); \
            cp16(wS + so_ + q_ * 16, wgp + (it_) * 32 + q_ * 4); \
        } \
    } while (0)

    C1_ISSUE(0); CP_COMMIT();
    C1_ISSUE(1); CP_COMMIT();

    for (int it = 0; it < C1_NIT; it++) {
        if (it < C1_NIT - 1) CP_WAIT1(); else CP_WAIT0();
        __syncthreads();
        uint32_t so = (it % 3) * 18432;
        #pragma unroll
        for (int ss = 0; ss < 4; ss++) {
            uint32_t ko = so + ss * 32;
            uint32_t af[4][4], b0q[4], b1q[4];
            #pragma unroll
            for (int i = 0; i < 4; i++) ldm4(af[i], aAddr[i] + ko);
            ldm4(b0q, bAddr + ko);
            ldm4(b1q, bAddr + ko + 16);
            #pragma unroll
            for (int i = 0; i < 4; i++)
                #pragma unroll
                for (int j = 0; j < 4; j++)
                    mma16(acc[i][j], af[i], b0q[j], b1q[j]);
        }
        if (it + 2 < C1_NIT) { C1_ISSUE(it + 2); CP_COMMIT(); }
    }

    float p = pw[0];
    #pragma unroll
    for (int j = 0; j < 4; j++) {
        int c = n0 + wn * 32 + 8 * j + 2 * fc;
        float s0 = rsqrtf(bvv[c] + EPSF) * bg[c];
        float o0 = bb[c] - bmu[c] * s0 + bias[c] * s0;
        float s1 = rsqrtf(bvv[c + 1] + EPSF) * bg[c + 1];
        float o1 = bb[c + 1] - bmu[c + 1] * s1 + bias[c + 1] * s1;
        #pragma unroll
        for (int i = 0; i < 4; i++) {
            int r0 = m0 + wm * 64 + 16 * i + fr;
            int r1 = r0 + 8;
            if (r0 < Lp_) {
                size_t nb = (size_t)b * Lp_ + r0;
                float v0 = acc[i][j][0] * s0 + o0;
                float v1 = acc[i][j][1] * s1 + o1;
                v0 = v0 > 0.f ? v0 : p * v0;
                v1 = v1 > 0.f ? v1 : p * v1;
                uint32_t pk = packbf(v0, v1);
                g_yh[nb * 128 + (c >> 1)]  = pk;
                g_xIh[nb * 128 + (c >> 1)] = pk;
            }
            if (r1 < Lp_) {
                size_t nb = (size_t)b * Lp_ + r1;
                float v2 = acc[i][j][2] * s0 + o0;
                float v3 = acc[i][j][3] * s1 + o1;
                v2 = v2 > 0.f ? v2 : p * v2;
                v3 = v3 > 0.f ? v3 : p * v3;
                uint32_t pk = packbf(v2, v3);
                g_yh[nb * 128 + (c >> 1)]  = pk;
                g_xIh[nb * 128 + (c >> 1)] = pk;
            }
        }
    }
}

// ---------------------------------------------------------------------------
// 3) cb GEMM: weight-resident multi-tile; k32 stages (32 iterations),
//    3-stage A ring. smem: 3*10240 + 67584 = 98304 B.
// ---------------------------------------------------------------------------
__global__ __launch_bounds__(256, 2) void cb_tc2(int blk, const float* __restrict__ bias)
{
    extern __shared__ uint32_t sm4[];
    __shared__ float sred[8];
    uint32_t sb = cvta_s(sm4);
    const uint32_t A0 = sb;                 // 3 stages * 10240 B
    const uint32_t W0 = sb + 30720;         // 128 rows * 528 B
    int n0 = blockIdx.x * 128;
    int tgrp = blockIdx.y;                  // 0..126, tiles tgrp*4 .. +3
    int t = threadIdx.x, lane = t & 31, wid = t >> 5;
    int wm = wid >> 2, wn = wid & 3;
    int fr = lane >> 2, fc = lane & 3;
    if (t < 8) sred[t] = 0.f;

    {
        const char* wbase = (const char*)g_cbwh + (size_t)(blk * 256 + n0) * 512;
        #pragma unroll
        for (int i = 0; i < 16; i++) {
            int c = t + 256 * i;
            int row = c >> 5, col = c & 31;
            cp16(W0 + row * 528 + col * 16, wbase + row * 512 + col * 16);
        }
    }

    int lr = t >> 1, seg = t & 1;
    const char* abase = (const char*)g_yh +
        ((size_t)(tgrp * 4) * 128 + lr) * 512 + seg * 32;
    uint32_t aS = A0 + lr * 80 + seg * 32;

    #define CB2_ISSUE(s_) do { \
        uint32_t d_ = aS + ((s_) % 3) * 10240; \
        const char* g_ = abase + (size_t)((s_) >> 3) * 65536 + ((s_) & 7) * 64; \
        cp16(d_, g_); cp16(d_ + 16, g_ + 16); \
    } while (0)

    CB2_ISSUE(0); CP_COMMIT();
    CB2_ISSUE(1); CP_COMMIT();

    uint32_t aAddr[4];
    #pragma unroll
    for (int i = 0; i < 4; i++)
        aAddr[i] = A0 + (wm * 64 + 16 * i + (lane & 15)) * 80 + ((lane & 16) ? 16 : 0);
    uint32_t bAddr = W0 + (wn * 32 + lane) * 528;

    float acc[4][4][4];
    float* psl = g_psum2 + blk * B_ * G_ * 2;

    for (int s = 0; s < CB_NIT; s++) {
        if ((s & 7) == 0) {
            #pragma unroll
            for (int i = 0; i < 4; i++)
                #pragma unroll
                for (int j = 0; j < 4; j++)
                    #pragma unroll
                    for (int q = 0; q < 4; q++) acc[i][j][q] = 0.f;
        }
        if (s < CB_NIT - 1) CP_WAIT1(); else CP_WAIT0();
        __syncthreads();
        {
            uint32_t so = (s % 3) * 10240;
            #pragma unroll
            for (int ss = 0; ss < 2; ss++) {
                uint32_t ko = so + ss * 32;
                uint32_t kw = (((s & 7) * 2) + ss) * 32;   // K-step within tile
                uint32_t af[4][4], b0q[4], b1q[4];
                #pragma unroll
                for (int i = 0; i < 4; i++) ldm4(af[i], aAddr[i] + ko);
                ldm4(b0q, bAddr + kw);
                ldm4(b1q, bAddr + kw + 16);
                #pragma unroll
                for (int i = 0; i < 4; i++)
                    #pragma unroll
                    for (int j = 0; j < 4; j++)
                        mma16(acc[i][j], af[i], b0q[j], b1q[j]);
            }
        }
        if (s + 2 < CB_NIT) { CB2_ISSUE(s + 2); CP_COMMIT(); }

        if ((s & 7) == 7) {
            int tile = tgrp * 4 + (s >> 3);
            int m0 = tile * 128;
            float rs[4][2], rq[4][2];
            #pragma unroll
            for (int i = 0; i < 4; i++) { rs[i][0] = rs[i][1] = rq[i][0] = rq[i][1] = 0.f; }
            #pragma unroll
            for (int j = 0; j < 4; j++) {
                int c = n0 + wn * 32 + 8 * j + 2 * fc;
                int cp = c >> 1;
                float bi0 = bias[c], bi1 = bias[c + 1];
                #pragma unroll
                for (int i = 0; i < 4; i++) {
                    size_t r0 = m0 + wm * 64 + 16 * i + fr;
                    size_t r1 = r0 + 8;
                    float v0 = acc[i][j][0] + bi0, v1 = acc[i][j][1] + bi1;
                    float v2 = acc[i][j][2] + bi0, v3 = acc[i][j][3] + bi1;
                    g_zh[r0 * 128 + cp] = packbf(v0, v1);
                    g_zh[r1 * 128 + cp] = packbf(v2, v3);
                    rs[i][0] += v0 + v1; rq[i][0] += v0 * v0 + v1 * v1;
                    rs[i][1] += v2 + v3; rq[i][1] += v2 * v2 + v3 * v3;
                }
            }
            int b0v = m0 / Lp_;
            int thr = (b0v + 1) * Lp_;
            float s0 = 0.f, q0 = 0.f, s1 = 0.f, q1 = 0.f;
            #pragma unroll
            for (int i = 0; i < 4; i++) {
                int r0 = m0 + wm * 64 + 16 * i + fr;
                if (r0 >= thr) { s1 += rs[i][0]; q1 += rq[i][0]; }
                else           { s0 += rs[i][0]; q0 += rq[i][0]; }
                if (r0 + 8 >= thr) { s1 += rs[i][1]; q1 += rq[i][1]; }
                else               { s0 += rs[i][1]; q0 += rq[i][1]; }
            }
            #pragma unroll
            for (int o = 16; o > 0; o >>= 1) {
                s0 += __shfl_xor_sync(0xffffffffu, s0, o);
                q0 += __shfl_xor_sync(0xffffffffu, q0, o);
                s1 += __shfl_xor_sync(0xffffffffu, s1, o);
                q1 += __shfl_xor_sync(0xffffffffu, q1, o);
            }
            int gslot = wn >> 1;
            if (lane == 0) {
                atomicAdd(&sred[gslot * 2 + 0], s0);
                atomicAdd(&sred[gslot * 2 + 1], q0);
                atomicAdd(&sred[4 + gslot * 2 + 0], s1);
                atomicAdd(&sred[4 + gslot * 2 + 1], q1);
            }
            __syncthreads();
            if (t < 8) {
                int bslot = t >> 2, gs = (t >> 1) & 1, sq = t & 1;
                int bb = b0v + bslot;
                if (bb < B_) {
                    int g = (n0 >> 6) + gs;
                    atomicAdd(&psl[(bb * G_ + g) * 2 + sq], sred[t]);
                }
                sred[t] = 0.f;
            }
            __syncthreads();
        }
    }
}

// ---------------------------------------------------------------------------
// 5) GroupNorm apply + PReLU + residual, bf16 y-chain; inline stats
// ---------------------------------------------------------------------------
__global__ void gnapply_kernel(int blk,
                               const float* __restrict__ gamma,
                               const float* __restrict__ beta,
                               const float* __restrict__ pp)
{
    unsigned idx = blockIdx.x * 256u + threadIdx.x;
    if (idx >= (unsigned)NB_ * 128u) return;
    unsigned nb = idx >> 7, wp = idx & 127;
    unsigned w0 = wp * 2;
    unsigned b = nb / Lp_;
    float2 st = gn_stats(blk, b, w0 >> 6);
    float ga0 = gamma[w0] * st.y,     be0 = beta[w0] - st.x * ga0;
    float ga1 = gamma[w0 + 1] * st.y, be1 = beta[w0 + 1] - st.x * ga1;
    float p = pp[0];
    uint32_t zu = g_zh[(size_t)nb * 128 + wp];
    uint32_t yu = g_yh[(size_t)nb * 128 + wp];
    float v0 = bf_lo(zu) * ga0 + be0; v0 = v0 > 0.f ? v0 : p * v0;
    float v1 = bf_hi(zu) * ga1 + be1; v1 = v1 > 0.f ? v1 : p * v1;
    float y0 = bf_lo(yu) + v0;
    float y1 = bf_hi(yu) + v1;
    g_yh[(size_t)nb * 128 + wp] = packbf(y0, y1);
}

// ---------------------------------------------------------------------------
// 6a) FINAL iter partial: gnapply + residual + xI + masked max over l-chunk
// ---------------------------------------------------------------------------
__global__ void pmax_kernel(int blk,
                            const int* __restrict__ posE,
                            const float* __restrict__ gamma,
                            const float* __restrict__ beta,
                            const float* __restrict__ pp)
{
    int b = blockIdx.x, ch = blockIdx.y, w = threadIdx.x;
    int p0 = posE[b * 2] + 1;
    int p1 = posE[b * 2 + 1] + 1;
    float2 st = gn_stats(blk, b, w >> 6);
    float ga = gamma[w] * st.y;
    float be = beta[w] - st.x * ga;
    float p = pp[0];
    int half = w & 1;
    float m1 = FNEG, m2 = FNEG, m3 = FNEG;
    int l0 = ch * 64;
    int l1 = l0 + 64 < Lp_ ? l0 + 64 : Lp_;
    const uint32_t* zp = g_zh  + (size_t)(b * Lp_ + l0) * 128 + (w >> 1);
    const uint32_t* yp = g_yh  + (size_t)(b * Lp_ + l0) * 128 + (w >> 1);
    const uint32_t* xp = g_xIh + (size_t)(b * Lp_ + l0) * 128 + (w >> 1);
    #pragma unroll 4
    for (int l = l0; l < l1; l++) {
        size_t d = (size_t)(l - l0) * 128;
        uint32_t zu = zp[d];
        uint32_t yu = yp[d];
        uint32_t xu = xp[d];
        float z  = half ? bf_hi(zu) : bf_lo(zu);
        float y  = half ? bf_hi(yu) : bf_lo(yu);
        float xi = half ? bf_hi(xu) : bf_lo(xu);
        float v = z * ga + be;
        v = v > 0.f ? v : p * v;
        float s = y + v + xi;
        float a1 = s + ((l >= p0) ? NEGF : 0.f);
        float a2 = s + ((l < p0 || l >= p1) ? NEGF : 0.f);
        float a3 = s + ((l < p1) ? NEGF : 0.f);
        m1 = fmaxf(m1, a1);
        m2 = fmaxf(m2, a2);
        m3 = fmaxf(m3, a3);
    }
    int base = ((b * NCH + ch) * 3) * W_ + w;
    g_pmax[base] = m1;
    g_pmax[base + W_] = m2;
    g_pmax[base + 2 * W_] = m3;
}

// ---------------------------------------------------------------------------
// 7) dense head + softmax; fused pmax reduction preamble
// ---------------------------------------------------------------------------
__global__ void dense_kernel(
    const float* __restrict__ d0w, const float* __restrict__ d0b,
    const float* __restrict__ d1w, const float* __restrict__ d1b,
    const float* __restrict__ bndg, const float* __restrict__ bndb,
    const float* __restrict__ bndm, const float* __restrict__ bndv,
    const float* __restrict__ pd,
    const float* __restrict__ finw, const float* __restrict__ finb,
    float* __restrict__ out)
{
    __shared__ float sf[3 * W_];
    __shared__ float sh[W_];
    __shared__ float sl[LBL_];
    __shared__ float red[2];
    int b = blockIdx.x, t = threadIdx.x;

    {
        float m1 = FNEG, m2 = FNEG, m3 = FNEG;
        #pragma unroll
        for (int ch = 0; ch < NCH; ch++) {
            int base = ((b * NCH + ch) * 3) * W_ + t;
            m1 = fmaxf(m1, g_pmax[base]);
            m2 = fmaxf(m2, g_pmax[base + W_]);
            m3 = fmaxf(m3, g_pmax[base + 2 * W_]);
        }
        sf[t] = m1;
        sf[W_ + t] = m2;
        sf[2 * W_ + t] = m3;
    }
    __syncthreads();

    float acc = d0b[t];
    {
        const float* wr = d0w + t * (3 * W_);
        #pragma unroll 8
        for (int k = 0; k < 3 * W_; k++) acc += sf[k] * wr[k];
    }
    acc = (acc - bndm[t]) * rsqrtf(bndv[t] + EPSF) * bndg[t] + bndb[t];
    { float p = pd[0]; acc = acc > 0.f ? acc : p * acc; }
    sh[t] = acc;
    __syncthreads();

    float a2 = d1b[t];
    {
        const float* wr = d1w + t * W_;
        #pragma unroll 8
        for (int k = 0; k < W_; k++) a2 += sh[k] * wr[k];
    }
    a2 = (a2 - bndm[W_ + t]) * rsqrtf(bndv[W_ + t] + EPSF) * bndg[W_ + t] + bndb[W_ + t];
    { float p = pd[1]; a2 = a2 > 0.f ? a2 : p * a2; }
    __syncthreads();
    sh[t] = a2;
    __syncthreads();

    if (t < LBL_) {
        float a3 = finb[t];
        const float* wr = finw + t * W_;
        #pragma unroll 8
        for (int k = 0; k < W_; k++) a3 += sh[k] * wr[k];
        sl[t] = a3;
    }
    __syncthreads();
    if (t == 0) {
        float mx = FNEG;
        for (int i = 0; i < LBL_; i++) mx = fmaxf(mx, sl[i]);
        float s = 0.f;
        for (int i = 0; i < LBL_; i++) s += expf(sl[i] - mx);
        red[0] = mx;
        red[1] = 1.f / s;
    }
    __syncthreads();
    if (t < LBL_) out[b * LBL_ + t] = expf(sl[t] - red[0]) * red[1];
}

// ---------------------------------------------------------------------------
// launch
// ---------------------------------------------------------------------------
extern "C" void kernel_launch(void* const* d_in, const int* in_sizes, int n_in,
                              void* d_out, int out_size)
{
    const int*   x      = (const int*)d_in[0];
    const int*   posE   = (const int*)d_in[1];
    const float* pe     = (const float*)d_in[2];
    const float* emb    = (const float*)d_in[3];
    const float* c1w    = (const float*)d_in[4];
    const float* c1b    = (const float*)d_in[5];
    const float* bn1g   = (const float*)d_in[6];
    const float* bn1b   = (const float*)d_in[7];
    const float* bn1m   = (const float*)d_in[8];
    const float* bn1v   = (const float*)d_in[9];
    const float* p1w    = (const float*)d_in[10];
    const float* cbw    = (const float*)d_in[11];
    const float* cbb    = (const float*)d_in[12];
    const float* gng    = (const float*)d_in[13];
    const float* gnb    = (const float*)d_in[14];
    const float* cbp    = (const float*)d_in[15];
    const float* d0w    = (const float*)d_in[16];
    const float* d0b    = (const float*)d_in[17];
    const float* d1w    = (const float*)d_in[18];
    const float* d1b    = (const float*)d_in[19];
    const float* bndg   = (const float*)d_in[20];
    const float* bndb   = (const float*)d_in[21];
    const float* bndm   = (const float*)d_in[22];
    const float* bndv   = (const float*)d_in[23];
    const float* pd     = (const float*)d_in[24];
    const float* finw   = (const float*)d_in[25];
    const float* finb   = (const float*)d_in[26];
    float* out = (float*)d_out;

    const int C1_SMEM = 110592;   // 3 * (18432 + 18432)
    const int CB2_SMEM = 98304;   // 3 * 10240 + 67584
    cudaFuncSetAttribute(conv1_tc, cudaFuncAttributeMaxDynamicSharedMemorySize, C1_SMEM);
    cudaFuncSetAttribute(cb_tc2,   cudaFuncAttributeMaxDynamicSharedMemorySize, CB2_SMEM);

    prep_w1h<<<(W_ * K1PW + 255) / 256, 256>>>(c1w);
    prep_cbwh<<<(CN_ * W_ * 128 + 255) / 256, 256>>>(cbw);
    embed_h<<<(B_ * L_ * HROW + 4096 + 255) / 256, 256>>>(x, pe, emb);

    {
        dim3 grid(W_ / 128, 4, B_);   // (w-tiles, n-tiles, b)
        conv1_tc<<<grid, 256, C1_SMEM>>>(c1b, bn1g, bn1b, bn1m, bn1v, p1w);
    }

    for (int i = 0; i < CN_; i++) {
        dim3 gridc(2, 127);           // (w-tiles, tile-groups of 4)
        cb_tc2<<<gridc, 256, CB2_SMEM>>>(i, cbb + i * W_);
        if (i < CN_ - 1) {
            gnapply_kernel<<<(NB_ * 128 + 255) / 256, 256>>>(
                i, gng + i * W_, gnb + i * W_, cbp + i);
        } else {
            dim3 gp(B_, NCH);
            pmax_kernel<<<gp, W_>>>(i, posE, gng + i * W_, gnb + i * W_, cbp + i);
        }
    }

    dense_kernel<<<B_, 256>>>(d0w, d0b, d1w, d1b, bndg, bndb, bndm, bndv,
                              pd, finw, finb, out);

    (void)in_sizes; (void)n_in; (void)out_size;
}

// round 13
// speedup vs baseline: 1.0121x; 1.0121x over previous
#include <cuda_runtime.h>
#include <cuda_bf16.h>
#include <cstdint>

// Problem constants
#define B_   128
#define L_   512
#define W_   256
#define CN_  4
#define G_   4
#define Lp_  508            // L - KH + 1
#define NB_  65024          // B_*Lp_ = 508*128 exactly
#define LBL_ 53
#define EPSF 1e-5f
#define NEGF (-100000.0f)
#define FNEG (-3.0e38f)
#define GCNT 32512.0f       // 64 * Lp_

#define HROW 68             // b32 per l row of h (136 bf16: 130 data + 6 pad)
#define K1PW 352            // b32 k-pairs per conv1 weight row (704 bf16)
#define C1_NIT 22           // 352/16 b32 (k32 bf16 per stage)
#define CB_NIT 64           // 64 k16-steps (4 tiles x 16)
#define NCH 8               // l-chunks for partial max

// Scratch (static device memory -- no allocations allowed)
__device__ uint32_t g_hb[(size_t)B_ * L_ * HROW + 4096]; // bf16-pair h, [b*L+l][68]
__device__ uint32_t g_w1h[(size_t)W_ * K1PW];            // conv1 w [w][352]
__device__ uint32_t g_cbwh[(size_t)CN_ * W_ * 128];      // cb w, bf16 [i][256][128 b32]
__device__ uint32_t g_yh[(size_t)NB_ * 128];             // y bf16 pairs [nb][128 b32]
__device__ uint32_t g_xIh[(size_t)NB_ * 128];            // xI bf16 pairs [nb][128 b32]
__device__ uint32_t g_zh[(size_t)NB_ * 128];             // z bf16 pairs [nb][128 b32]
__device__ float    g_psum2[CN_ * B_ * G_ * 2];          // per-layer (sum, sumsq)
__device__ float    g_pmax[B_ * NCH * 3 * W_];

// ---------------------------------------------------------------------------
// helpers
// ---------------------------------------------------------------------------
__device__ __forceinline__ uint32_t cvta_s(const void* p) {
    return (uint32_t)__cvta_generic_to_shared(p);
}
__device__ __forceinline__ void cp16(uint32_t s, const void* g) {
    asm volatile("cp.async.cg.shared.global [%0],[%1],16;" :: "r"(s), "l"(g));
}
#define CP_COMMIT() asm volatile("cp.async.commit_group;")
#define CP_WAIT2()  asm volatile("cp.async.wait_group 2;")
#define CP_WAIT1()  asm volatile("cp.async.wait_group 1;")
#define CP_WAIT0()  asm volatile("cp.async.wait_group 0;")

__device__ __forceinline__ void ldm4(uint32_t* r, uint32_t addr) {
    asm volatile("ldmatrix.sync.aligned.m8n8.x4.shared.b16 {%0,%1,%2,%3}, [%4];"
        : "=r"(r[0]), "=r"(r[1]), "=r"(r[2]), "=r"(r[3]) : "r"(addr));
}

__device__ __forceinline__ void mma16(float* c, const uint32_t* a,
                                      uint32_t b0, uint32_t b1) {
    asm volatile(
        "mma.sync.aligned.m16n8k16.row.col.f32.bf16.bf16.f32 "
        "{%0,%1,%2,%3}, {%4,%5,%6,%7}, {%8,%9}, {%0,%1,%2,%3};"
        : "+f"(c[0]), "+f"(c[1]), "+f"(c[2]), "+f"(c[3])
        : "r"(a[0]), "r"(a[1]), "r"(a[2]), "r"(a[3]), "r"(b0), "r"(b1));
}

__device__ __forceinline__ uint32_t packbf(float lo, float hi) {
    __nv_bfloat162 t = __floats2bfloat162_rn(lo, hi);
    return *(uint32_t*)&t;
}
__device__ __forceinline__ float bf_lo(uint32_t u) {
    __nv_bfloat162 t = *(__nv_bfloat162*)&u;
    return __bfloat162float(t.x);
}
__device__ __forceinline__ float bf_hi(uint32_t u) {
    __nv_bfloat162 t = *(__nv_bfloat162*)&u;
    return __bfloat162float(t.y);
}
__device__ __forceinline__ float2 gn_stats(int blk, int b, int g) {
    const float* ps = g_psum2 + ((blk * B_ + b) * G_ + g) * 2;
    float s = __ldg(ps), q = __ldg(ps + 1);
    float mean = s / GCNT;
    float var  = q / GCNT - mean * mean;
    return make_float2(mean, rsqrtf(var + EPSF));
}

// ---------------------------------------------------------------------------
// 0a) conv1 weight prep: [w][650] fp32 -> [w][352] bf16-pair (window layout)
// ---------------------------------------------------------------------------
__global__ void prep_w1h(const float* __restrict__ w)
{
    int idx = blockIdx.x * 256 + threadIdx.x;
    if (idx >= W_ * K1PW) return;
    int m = idx / K1PW, kp = idx - m * K1PW;
    int ks = 2 * kp;
    float v0 = 0.f, v1 = 0.f;
    int seg0 = ks / 136, off0 = ks - seg0 * 136;
    if (seg0 < 5 && off0 < 130)     v0 = w[m * 650 + seg0 * 130 + off0];
    int ks1 = ks + 1;
    int seg1 = ks1 / 136, off1 = ks1 - seg1 * 136;
    if (seg1 < 5 && off1 < 130)     v1 = w[m * 650 + seg1 * 130 + off1];
    g_w1h[idx] = packbf(v0, v1);
}

// ---------------------------------------------------------------------------
// 0b) cb weight prep + per-layer psum zero init (once)
// ---------------------------------------------------------------------------
__global__ void prep_cbwh(const float* __restrict__ w)
{
    int idx = blockIdx.x * 256 + threadIdx.x;
    if (idx < CN_ * B_ * G_ * 2) g_psum2[idx] = 0.f;
    if (idx >= CN_ * W_ * 128) return;
    int row = idx >> 7;
    int kp  = idx & 127;
    const float* src = w + (size_t)row * W_ + 2 * kp;
    g_cbwh[idx] = packbf(src[0], src[1]);
}

// ---------------------------------------------------------------------------
// 1) embedding + position -> g_hb bf16 pairs [b*L+l][68]; zeros pad + tail
// ---------------------------------------------------------------------------
__global__ void embed_h(const int* __restrict__ x,
                        const float* __restrict__ pe,
                        const float* __restrict__ emb)
{
    int id = blockIdx.x * 256 + threadIdx.x;
    const int MAIN = B_ * L_ * HROW;
    if (id >= MAIN + 4096) return;
    if (id >= MAIN) { g_hb[id] = 0u; return; }
    int bl = id / HROW, t = id - bl * HROW;
    float v0 = 0.f, v1 = 0.f;
    if (t < 64) {
        int tok = x[bl];
        const float* e = emb + (size_t)tok * 128 + 2 * t;
        v0 = e[0]; v1 = e[1];
    } else if (t == 64) {
        v0 = pe[bl * 2]; v1 = pe[bl * 2 + 1];
    }
    g_hb[id] = packbf(v0, v1);
}

// ---------------------------------------------------------------------------
// 2) conv1: C[n][w] = window(h)[n][704] @ w1[w][704]^T, per-batch.
//    k32 stages (22 iterations), 3-stage ring. Row pitch 80 B. (R10 config)
// ---------------------------------------------------------------------------
__global__ __launch_bounds__(256, 2) void conv1_tc(
    const float* __restrict__ bias,
    const float* __restrict__ bg, const float* __restrict__ bb,
    const float* __restrict__ bmu, const float* __restrict__ bvv,
    const float* __restrict__ pw)
{
    extern __shared__ uint32_t sm[];
    uint32_t sb = cvta_s(sm);
    int b  = blockIdx.z;
    int m0 = blockIdx.y * 128;     // n-position tile
    int n0 = blockIdx.x * 128;     // w tile
    int t = threadIdx.x, lane = t & 31, wid = t >> 5;
    int wm = wid >> 2, wn = wid & 3;
    int fr = lane >> 2, fc = lane & 3;

    float acc[4][4][4];
    #pragma unroll
    for (int i = 0; i < 4; i++)
        #pragma unroll
        for (int j = 0; j < 4; j++)
            #pragma unroll
            for (int q = 0; q < 4; q++) acc[i][j][q] = 0.f;

    int lr = t >> 1, lc = (t & 1) * 8;
    const uint32_t* agp = g_hb + (size_t)(b * 512 + m0 + lr) * HROW + lc;
    const uint32_t* wgp = g_w1h + (size_t)(n0 + lr) * K1PW + lc;
    uint32_t aS = sb + lr * 80 + lc * 4;
    uint32_t wS = sb + 30720 + lr * 80 + lc * 4;

    uint32_t aAddr[4];
    #pragma unroll
    for (int i = 0; i < 4; i++) {
        int row = wm * 64 + 16 * i + (lane & 15);
        int col = (lane & 16) ? 4 : 0;
        aAddr[i] = sb + row * 80 + col * 4;
    }
    uint32_t bAddr = sb + 30720 + (wn * 32 + lane) * 80;

    #define C1_ISSUE(it_) do { \
        uint32_t so_ = ((it_) % 3) * 10240; \
        cp16(aS + so_, agp + (it_) * 16); \
        cp16(aS + so_ + 16, agp + (it_) * 16 + 4); \
        cp16(wS + so_, wgp + (it_) * 16); \
        cp16(wS + so_ + 16, wgp + (it_) * 16 + 4); \
    } while (0)

    C1_ISSUE(0); CP_COMMIT();
    C1_ISSUE(1); CP_COMMIT();

    for (int it = 0; it < C1_NIT; it++) {
        if (it < C1_NIT - 1) CP_WAIT1(); else CP_WAIT0();
        __syncthreads();
        uint32_t so = (it % 3) * 10240;
        #pragma unroll
        for (int ss = 0; ss < 2; ss++) {
            uint32_t ko = so + ss * 32;
            uint32_t af[4][4], b0q[4], b1q[4];
            #pragma unroll
            for (int i = 0; i < 4; i++) ldm4(af[i], aAddr[i] + ko);
            ldm4(b0q, bAddr + ko);
            ldm4(b1q, bAddr + ko + 16);
            #pragma unroll
            for (int i = 0; i < 4; i++)
                #pragma unroll
                for (int j = 0; j < 4; j++)
                    mma16(acc[i][j], af[i], b0q[j], b1q[j]);
        }
        if (it + 2 < C1_NIT) { C1_ISSUE(it + 2); CP_COMMIT(); }
    }

    float p = pw[0];
    #pragma unroll
    for (int j = 0; j < 4; j++) {
        int c = n0 + wn * 32 + 8 * j + 2 * fc;
        float s0 = rsqrtf(bvv[c] + EPSF) * bg[c];
        float o0 = bb[c] - bmu[c] * s0 + bias[c] * s0;
        float s1 = rsqrtf(bvv[c + 1] + EPSF) * bg[c + 1];
        float o1 = bb[c + 1] - bmu[c + 1] * s1 + bias[c + 1] * s1;
        #pragma unroll
        for (int i = 0; i < 4; i++) {
            int r0 = m0 + wm * 64 + 16 * i + fr;
            int r1 = r0 + 8;
            if (r0 < Lp_) {
                size_t nb = (size_t)b * Lp_ + r0;
                float v0 = acc[i][j][0] * s0 + o0;
                float v1 = acc[i][j][1] * s1 + o1;
                v0 = v0 > 0.f ? v0 : p * v0;
                v1 = v1 > 0.f ? v1 : p * v1;
                uint32_t pk = packbf(v0, v1);
                g_yh[nb * 128 + (c >> 1)]  = pk;
                g_xIh[nb * 128 + (c >> 1)] = pk;
            }
            if (r1 < Lp_) {
                size_t nb = (size_t)b * Lp_ + r1;
                float v2 = acc[i][j][2] * s0 + o0;
                float v3 = acc[i][j][3] * s1 + o1;
                v2 = v2 > 0.f ? v2 : p * v2;
                v3 = v3 > 0.f ? v3 : p * v3;
                uint32_t pk = packbf(v2, v3);
                g_yh[nb * 128 + (c >> 1)]  = pk;
                g_xIh[nb * 128 + (c >> 1)] = pk;
            }
        }
    }
}

// ---------------------------------------------------------------------------
// 3) cb GEMM: weight-resident multi-tile; k16 stages, 4-stage A ring.
//    (R10 config) smem: 4*6144 + 67584 = 92160 B.
// ---------------------------------------------------------------------------
__global__ __launch_bounds__(256, 2) void cb_tc2(int blk, const float* __restrict__ bias)
{
    extern __shared__ uint32_t sm4[];
    __shared__ float sred[8];
    uint32_t sb = cvta_s(sm4);
    const uint32_t A0 = sb;                 // 4 stages * 6144 B
    const uint32_t W0 = sb + 24576;         // 128 rows * 528 B
    int n0 = blockIdx.x * 128;
    int tgrp = blockIdx.y;                  // 0..126, tiles tgrp*4 .. +3
    int t = threadIdx.x, lane = t & 31, wid = t >> 5;
    int wm = wid >> 2, wn = wid & 3;
    int fr = lane >> 2, fc = lane & 3;
    if (t < 8) sred[t] = 0.f;

    {
        const char* wbase = (const char*)g_cbwh + (size_t)(blk * 256 + n0) * 512;
        #pragma unroll
        for (int i = 0; i < 16; i++) {
            int c = t + 256 * i;
            int row = c >> 5, col = c & 31;
            cp16(W0 + row * 528 + col * 16, wbase + row * 512 + col * 16);
        }
    }

    int arow = t >> 1, ahalf = t & 1;
    const char* abase = (const char*)g_yh +
        ((size_t)(tgrp * 4) * 128 + arow) * 512 + ahalf * 16;
    uint32_t aS = A0 + arow * 48 + ahalf * 16;

    #define CB2_ISSUE(s_) \
        cp16(aS + ((s_) & 3) * 6144, \
             abase + (size_t)((s_) >> 4) * 65536 + ((s_) & 15) * 32)

    CB2_ISSUE(0); CP_COMMIT();
    CB2_ISSUE(1); CP_COMMIT();
    CB2_ISSUE(2); CP_COMMIT();

    uint32_t aAddr[4];
    #pragma unroll
    for (int i = 0; i < 4; i++)
        aAddr[i] = A0 + (wm * 64 + 16 * i + (lane & 15)) * 48 + ((lane & 16) ? 16 : 0);
    uint32_t bAddr = W0 + (wn * 32 + lane) * 528;

    float acc[4][4][4];
    float* psl = g_psum2 + blk * B_ * G_ * 2;

    for (int s = 0; s < CB_NIT; s++) {
        if ((s & 15) == 0) {
            #pragma unroll
            for (int i = 0; i < 4; i++)
                #pragma unroll
                for (int j = 0; j < 4; j++)
                    #pragma unroll
                    for (int q = 0; q < 4; q++) acc[i][j][q] = 0.f;
        }
        if (s < 62) CP_WAIT2(); else if (s == 62) CP_WAIT1(); else CP_WAIT0();
        __syncthreads();
        {
            uint32_t so = (s & 3) * 6144;
            uint32_t ko = (s & 15) * 32;
            uint32_t af[4][4], b0q[4], b1q[4];
            #pragma unroll
            for (int i = 0; i < 4; i++) ldm4(af[i], aAddr[i] + so);
            ldm4(b0q, bAddr + ko);
            ldm4(b1q, bAddr + ko + 16);
            #pragma unroll
            for (int i = 0; i < 4; i++)
                #pragma unroll
                for (int j = 0; j < 4; j++)
                    mma16(acc[i][j], af[i], b0q[j], b1q[j]);
        }
        if (s + 3 < CB_NIT) { CB2_ISSUE(s + 3); CP_COMMIT(); }

        if ((s & 15) == 15) {
            int tile = tgrp * 4 + (s >> 4);
            int m0 = tile * 128;
            float rs[4][2], rq[4][2];
            #pragma unroll
            for (int i = 0; i < 4; i++) { rs[i][0] = rs[i][1] = rq[i][0] = rq[i][1] = 0.f; }
            #pragma unroll
            for (int j = 0; j < 4; j++) {
                int c = n0 + wn * 32 + 8 * j + 2 * fc;
                int cp = c >> 1;
                float bi0 = bias[c], bi1 = bias[c + 1];
                #pragma unroll
                for (int i = 0; i < 4; i++) {
                    size_t r0 = m0 + wm * 64 + 16 * i + fr;
                    size_t r1 = r0 + 8;
                    float v0 = acc[i][j][0] + bi0, v1 = acc[i][j][1] + bi1;
                    float v2 = acc[i][j][2] + bi0, v3 = acc[i][j][3] + bi1;
                    g_zh[r0 * 128 + cp] = packbf(v0, v1);
                    g_zh[r1 * 128 + cp] = packbf(v2, v3);
                    rs[i][0] += v0 + v1; rq[i][0] += v0 * v0 + v1 * v1;
                    rs[i][1] += v2 + v3; rq[i][1] += v2 * v2 + v3 * v3;
                }
            }
            int b0v = m0 / Lp_;
            int thr = (b0v + 1) * Lp_;
            float s0 = 0.f, q0 = 0.f, s1 = 0.f, q1 = 0.f;
            #pragma unroll
            for (int i = 0; i < 4; i++) {
                int r0 = m0 + wm * 64 + 16 * i + fr;
                if (r0 >= thr) { s1 += rs[i][0]; q1 += rq[i][0]; }
                else           { s0 += rs[i][0]; q0 += rq[i][0]; }
                if (r0 + 8 >= thr) { s1 += rs[i][1]; q1 += rq[i][1]; }
                else               { s0 += rs[i][1]; q0 += rq[i][1]; }
            }
            #pragma unroll
            for (int o = 16; o > 0; o >>= 1) {
                s0 += __shfl_xor_sync(0xffffffffu, s0, o);
                q0 += __shfl_xor_sync(0xffffffffu, q0, o);
                s1 += __shfl_xor_sync(0xffffffffu, s1, o);
                q1 += __shfl_xor_sync(0xffffffffu, q1, o);
            }
            int gslot = wn >> 1;
            if (lane == 0) {
                atomicAdd(&sred[gslot * 2 + 0], s0);
                atomicAdd(&sred[gslot * 2 + 1], q0);
                atomicAdd(&sred[4 + gslot * 2 + 0], s1);
                atomicAdd(&sred[4 + gslot * 2 + 1], q1);
            }
            __syncthreads();
            if (t < 8) {
                int bslot = t >> 2, gs = (t >> 1) & 1, sq = t & 1;
                int bb = b0v + bslot;
                if (bb < B_) {
                    int g = (n0 >> 6) + gs;
                    atomicAdd(&psl[(bb * G_ + g) * 2 + sq], sred[t]);
                }
                sred[t] = 0.f;
            }
            __syncthreads();
        }
    }
}

// ---------------------------------------------------------------------------
// 5) GroupNorm apply + PReLU + residual, bf16 y-chain; uint4 per thread
//    (8 channels). 8-channel span never crosses a 64-channel group.
// ---------------------------------------------------------------------------
__global__ void gnapply_kernel(int blk,
                               const float* __restrict__ gamma,
                               const float* __restrict__ beta,
                               const float* __restrict__ pp)
{
    unsigned i4 = blockIdx.x * 256u + threadIdx.x;
    if (i4 >= (unsigned)NB_ * 32u) return;
    unsigned nb = i4 >> 5, q = i4 & 31;
    unsigned wp0 = q * 4;
    unsigned w0 = wp0 * 2;
    unsigned b = nb / Lp_;
    float2 st = gn_stats(blk, b, w0 >> 6);
    float p = pp[0];
    float ga[8], be[8];
    #pragma unroll
    for (int k = 0; k < 8; k++) {
        ga[k] = gamma[w0 + k] * st.y;
        be[k] = beta[w0 + k] - st.x * ga[k];
    }
    size_t o = (size_t)nb * 128 + wp0;
    uint4 z4 = *(const uint4*)(g_zh + o);
    uint4 y4 = *(const uint4*)(g_yh + o);
    uint32_t zw[4] = {z4.x, z4.y, z4.z, z4.w};
    uint32_t yw[4] = {y4.x, y4.y, y4.z, y4.w};
    uint32_t rw[4];
    #pragma unroll
    for (int k = 0; k < 4; k++) {
        float v0 = bf_lo(zw[k]) * ga[2 * k] + be[2 * k];
        v0 = v0 > 0.f ? v0 : p * v0;
        float v1 = bf_hi(zw[k]) * ga[2 * k + 1] + be[2 * k + 1];
        v1 = v1 > 0.f ? v1 : p * v1;
        rw[k] = packbf(bf_lo(yw[k]) + v0, bf_hi(yw[k]) + v1);
    }
    *(uint4*)(g_yh + o) = make_uint4(rw[0], rw[1], rw[2], rw[3]);
}

// ---------------------------------------------------------------------------
// 6a) FINAL iter partial: gnapply + residual + xI + masked max over l-chunk
// ---------------------------------------------------------------------------
__global__ void pmax_kernel(int blk,
                            const int* __restrict__ posE,
                            const float* __restrict__ gamma,
                            const float* __restrict__ beta,
                            const float* __restrict__ pp)
{
    int b = blockIdx.x, ch = blockIdx.y, w = threadIdx.x;
    int p0 = posE[b * 2] + 1;
    int p1 = posE[b * 2 + 1] + 1;
    float2 st = gn_stats(blk, b, w >> 6);
    float ga = gamma[w] * st.y;
    float be = beta[w] - st.x * ga;
    float p = pp[0];
    int half = w & 1;
    float m1 = FNEG, m2 = FNEG, m3 = FNEG;
    int l0 = ch * 64;
    int l1 = l0 + 64 < Lp_ ? l0 + 64 : Lp_;
    const uint32_t* zp = g_zh  + (size_t)(b * Lp_ + l0) * 128 + (w >> 1);
    const uint32_t* yp = g_yh  + (size_t)(b * Lp_ + l0) * 128 + (w >> 1);
    const uint32_t* xp = g_xIh + (size_t)(b * Lp_ + l0) * 128 + (w >> 1);
    #pragma unroll 4
    for (int l = l0; l < l1; l++) {
        size_t d = (size_t)(l - l0) * 128;
        uint32_t zu = zp[d];
        uint32_t yu = yp[d];
        uint32_t xu = xp[d];
        float z  = half ? bf_hi(zu) : bf_lo(zu);
        float y  = half ? bf_hi(yu) : bf_lo(yu);
        float xi = half ? bf_hi(xu) : bf_lo(xu);
        float v = z * ga + be;
        v = v > 0.f ? v : p * v;
        float s = y + v + xi;
        float a1 = s + ((l >= p0) ? NEGF : 0.f);
        float a2 = s + ((l < p0 || l >= p1) ? NEGF : 0.f);
        float a3 = s + ((l < p1) ? NEGF : 0.f);
        m1 = fmaxf(m1, a1);
        m2 = fmaxf(m2, a2);
        m3 = fmaxf(m3, a3);
    }
    int base = ((b * NCH + ch) * 3) * W_ + w;
    g_pmax[base] = m1;
    g_pmax[base + W_] = m2;
    g_pmax[base + 2 * W_] = m3;
}

// ---------------------------------------------------------------------------
// 7) dense head + softmax; fused pmax reduction preamble
// ---------------------------------------------------------------------------
__global__ void dense_kernel(
    const float* __restrict__ d0w, const float* __restrict__ d0b,
    const float* __restrict__ d1w, const float* __restrict__ d1b,
    const float* __restrict__ bndg, const float* __restrict__ bndb,
    const float* __restrict__ bndm, const float* __restrict__ bndv,
    const float* __restrict__ pd,
    const float* __restrict__ finw, const float* __restrict__ finb,
    float* __restrict__ out)
{
    __shared__ float sf[3 * W_];
    __shared__ float sh[W_];
    __shared__ float sl[LBL_];
    __shared__ float red[2];
    int b = blockIdx.x, t = threadIdx.x;

    {
        float m1 = FNEG, m2 = FNEG, m3 = FNEG;
        #pragma unroll
        for (int ch = 0; ch < NCH; ch++) {
            int base = ((b * NCH + ch) * 3) * W_ + t;
            m1 = fmaxf(m1, g_pmax[base]);
            m2 = fmaxf(m2, g_pmax[base + W_]);
            m3 = fmaxf(m3, g_pmax[base + 2 * W_]);
        }
        sf[t] = m1;
        sf[W_ + t] = m2;
        sf[2 * W_ + t] = m3;
    }
    __syncthreads();

    float acc = d0b[t];
    {
        const float* wr = d0w + t * (3 * W_);
        #pragma unroll 8
        for (int k = 0; k < 3 * W_; k++) acc += sf[k] * wr[k];
    }
    acc = (acc - bndm[t]) * rsqrtf(bndv[t] + EPSF) * bndg[t] + bndb[t];
    { float p = pd[0]; acc = acc > 0.f ? acc : p * acc; }
    sh[t] = acc;
    __syncthreads();

    float a2 = d1b[t];
    {
        const float* wr = d1w + t * W_;
        #pragma unroll 8
        for (int k = 0; k < W_; k++) a2 += sh[k] * wr[k];
    }
    a2 = (a2 - bndm[W_ + t]) * rsqrtf(bndv[W_ + t] + EPSF) * bndg[W_ + t] + bndb[W_ + t];
    { float p = pd[1]; a2 = a2 > 0.f ? a2 : p * a2; }
    __syncthreads();
    sh[t] = a2;
    __syncthreads();

    if (t < LBL_) {
        float a3 = finb[t];
        const float* wr = finw + t * W_;
        #pragma unroll 8
        for (int k = 0; k < W_; k++) a3 += sh[k] * wr[k];
        sl[t] = a3;
    }
    __syncthreads();
    if (t == 0) {
        float mx = FNEG;
        for (int i = 0; i < LBL_; i++) mx = fmaxf(mx, sl[i]);
        float s = 0.f;
        for (int i = 0; i < LBL_; i++) s += expf(sl[i] - mx);
        red[0] = mx;
        red[1] = 1.f / s;
    }
    __syncthreads();
    if (t < LBL_) out[b * LBL_ + t] = expf(sl[t] - red[0]) * red[1];
}

// ---------------------------------------------------------------------------
// launch
// ---------------------------------------------------------------------------
extern "C" void kernel_launch(void* const* d_in, const int* in_sizes, int n_in,
                              void* d_out, int out_size)
{
    const int*   x      = (const int*)d_in[0];
    const int*   posE   = (const int*)d_in[1];
    const float* pe     = (const float*)d_in[2];
    const float* emb    = (const float*)d_in[3];
    const float* c1w    = (const float*)d_in[4];
    const float* c1b    = (const float*)d_in[5];
    const float* bn1g   = (const float*)d_in[6];
    const float* bn1b   = (const float*)d_in[7];
    const float* bn1m   = (const float*)d_in[8];
    const float* bn1v   = (const float*)d_in[9];
    const float* p1w    = (const float*)d_in[10];
    const float* cbw    = (const float*)d_in[11];
    const float* cbb    = (const float*)d_in[12];
    const float* gng    = (const float*)d_in[13];
    const float* gnb    = (const float*)d_in[14];
    const float* cbp    = (const float*)d_in[15];
    const float* d0w    = (const float*)d_in[16];
    const float* d0b    = (const float*)d_in[17];
    const float* d1w    = (const float*)d_in[18];
    const float* d1b    = (const float*)d_in[19];
    const float* bndg   = (const float*)d_in[20];
    const float* bndb   = (const float*)d_in[21];
    const float* bndm   = (const float*)d_in[22];
    const float* bndv   = (const float*)d_in[23];
    const float* pd     = (const float*)d_in[24];
    const float* finw   = (const float*)d_in[25];
    const float* finb   = (const float*)d_in[26];
    float* out = (float*)d_out;

    const int GEMM_SMEM = 61440;
    const int CB2_SMEM  = 24576 + 67584;   // 92160
    cudaFuncSetAttribute(conv1_tc, cudaFuncAttributeMaxDynamicSharedMemorySize, GEMM_SMEM);
    cudaFuncSetAttribute(cb_tc2,   cudaFuncAttributeMaxDynamicSharedMemorySize, CB2_SMEM);

    prep_w1h<<<(W_ * K1PW + 255) / 256, 256>>>(c1w);
    prep_cbwh<<<(CN_ * W_ * 128 + 255) / 256, 256>>>(cbw);
    embed_h<<<(B_ * L_ * HROW + 4096 + 255) / 256, 256>>>(x, pe, emb);

    {
        dim3 grid(W_ / 128, 4, B_);   // (w-tiles, n-tiles, b)
        conv1_tc<<<grid, 256, GEMM_SMEM>>>(c1b, bn1g, bn1b, bn1m, bn1v, p1w);
    }

    for (int i = 0; i < CN_; i++) {
        dim3 gridc(2, 127);           // (w-tiles, tile-groups of 4)
        cb_tc2<<<gridc, 256, CB2_SMEM>>>(i, cbb + i * W_);
        if (i < CN_ - 1) {
            gnapply_kernel<<<(NB_ * 32 + 255) / 256, 256>>>(
                i, gng + i * W_, gnb + i * W_, cbp + i);
        } else {
            dim3 gp(B_, NCH);
            pmax_kernel<<<gp, W_>>>(i, posE, gng + i * W_, gnb + i * W_, cbp + i);
        }
    }

    dense_kernel<<<B_, 256>>>(d0w, d0b, d1w, d1b, bndg, bndb, bndm, bndv,
                              pd, finw, finb, out);

    (void)in_sizes; (void)n_in; (void)out_size;
}

// round 14
// speedup vs baseline: 1.0613x; 1.0487x over previous
#include <cuda_runtime.h>
#include <cuda_bf16.h>
#include <cstdint>

// Problem constants
#define B_   128
#define L_   512
#define W_   256
#define CN_  4
#define G_   4
#define Lp_  508            // L - KH + 1
#define NB_  65024          // B_*Lp_ = 508*128 exactly
#define LBL_ 53
#define EPSF 1e-5f
#define NEGF (-100000.0f)
#define FNEG (-3.0e38f)
#define GCNT 32512.0f       // 64 * Lp_

#define HROW 68             // b32 per l row of h (136 bf16: 130 data + 6 pad)
#define K1PW 352            // b32 k-pairs per conv1 weight row (704 bf16)
#define C1_NIT 22           // 352/16 b32 (k32 bf16 per stage)
#define CB_NIT 64           // 64 k16-steps (4 tiles x 16)
#define NCH 8               // l-chunks for partial max

// Scratch (static device memory -- no allocations allowed)
__device__ uint32_t g_hb[(size_t)B_ * L_ * HROW + 4096]; // bf16-pair h, [b*L+l][68]
__device__ uint32_t g_w1h[(size_t)W_ * K1PW];            // conv1 w [w][352]
__device__ uint32_t g_cbwh[(size_t)CN_ * W_ * 128];      // cb w, bf16 [i][256][128 b32]
__device__ uint32_t g_yh[(size_t)NB_ * 128];             // y bf16 pairs [nb][128 b32]
__device__ uint32_t g_xIh[(size_t)NB_ * 128];            // xI bf16 pairs [nb][128 b32]
__device__ uint32_t g_zh[(size_t)NB_ * 128];             // z bf16 pairs [nb][128 b32]
__device__ float    g_psum2[CN_ * B_ * G_ * 2];          // per-layer (sum, sumsq)
__device__ float    g_pmax[B_ * NCH * 3 * W_];

// ---------------------------------------------------------------------------
// helpers
// ---------------------------------------------------------------------------
__device__ __forceinline__ uint32_t cvta_s(const void* p) {
    return (uint32_t)__cvta_generic_to_shared(p);
}
__device__ __forceinline__ void cp16(uint32_t s, const void* g) {
    asm volatile("cp.async.cg.shared.global [%0],[%1],16;" :: "r"(s), "l"(g));
}
#define CP_COMMIT() asm volatile("cp.async.commit_group;")
#define CP_WAIT2()  asm volatile("cp.async.wait_group 2;")
#define CP_WAIT1()  asm volatile("cp.async.wait_group 1;")
#define CP_WAIT0()  asm volatile("cp.async.wait_group 0;")

__device__ __forceinline__ void ldm4(uint32_t* r, uint32_t addr) {
    asm volatile("ldmatrix.sync.aligned.m8n8.x4.shared.b16 {%0,%1,%2,%3}, [%4];"
        : "=r"(r[0]), "=r"(r[1]), "=r"(r[2]), "=r"(r[3]) : "r"(addr));
}

__device__ __forceinline__ void mma16(float* c, const uint32_t* a,
                                      uint32_t b0, uint32_t b1) {
    asm volatile(
        "mma.sync.aligned.m16n8k16.row.col.f32.bf16.bf16.f32 "
        "{%0,%1,%2,%3}, {%4,%5,%6,%7}, {%8,%9}, {%0,%1,%2,%3};"
        : "+f"(c[0]), "+f"(c[1]), "+f"(c[2]), "+f"(c[3])
        : "r"(a[0]), "r"(a[1]), "r"(a[2]), "r"(a[3]), "r"(b0), "r"(b1));
}

__device__ __forceinline__ uint32_t packbf(float lo, float hi) {
    __nv_bfloat162 t = __floats2bfloat162_rn(lo, hi);
    return *(uint32_t*)&t;
}
__device__ __forceinline__ float bf_lo(uint32_t u) {
    __nv_bfloat162 t = *(__nv_bfloat162*)&u;
    return __bfloat162float(t.x);
}
__device__ __forceinline__ float bf_hi(uint32_t u) {
    __nv_bfloat162 t = *(__nv_bfloat162*)&u;
    return __bfloat162float(t.y);
}
__device__ __forceinline__ float2 gn_stats(int blk, int b, int g) {
    const float* ps = g_psum2 + ((blk * B_ + b) * G_ + g) * 2;
    float s = __ldg(ps), q = __ldg(ps + 1);
    float mean = s / GCNT;
    float var  = q / GCNT - mean * mean;
    return make_float2(mean, rsqrtf(var + EPSF));
}

// ---------------------------------------------------------------------------
// 0a) conv1 weight prep: [w][650] fp32 -> [w][352] bf16-pair (window layout)
// ---------------------------------------------------------------------------
__global__ void prep_w1h(const float* __restrict__ w)
{
    int idx = blockIdx.x * 256 + threadIdx.x;
    if (idx >= W_ * K1PW) return;
    int m = idx / K1PW, kp = idx - m * K1PW;
    int ks = 2 * kp;
    float v0 = 0.f, v1 = 0.f;
    int seg0 = ks / 136, off0 = ks - seg0 * 136;
    if (seg0 < 5 && off0 < 130)     v0 = w[m * 650 + seg0 * 130 + off0];
    int ks1 = ks + 1;
    int seg1 = ks1 / 136, off1 = ks1 - seg1 * 136;
    if (seg1 < 5 && off1 < 130)     v1 = w[m * 650 + seg1 * 130 + off1];
    g_w1h[idx] = packbf(v0, v1);
}

// ---------------------------------------------------------------------------
// 0b) cb weight prep + per-layer psum zero init (once)
// ---------------------------------------------------------------------------
__global__ void prep_cbwh(const float* __restrict__ w)
{
    int idx = blockIdx.x * 256 + threadIdx.x;
    if (idx < CN_ * B_ * G_ * 2) g_psum2[idx] = 0.f;
    if (idx >= CN_ * W_ * 128) return;
    int row = idx >> 7;
    int kp  = idx & 127;
    const float* src = w + (size_t)row * W_ + 2 * kp;
    g_cbwh[idx] = packbf(src[0], src[1]);
}

// ---------------------------------------------------------------------------
// 1) embedding + position -> g_hb bf16 pairs [b*L+l][68]; zeros pad + tail
// ---------------------------------------------------------------------------
__global__ void embed_h(const int* __restrict__ x,
                        const float* __restrict__ pe,
                        const float* __restrict__ emb)
{
    int id = blockIdx.x * 256 + threadIdx.x;
    const int MAIN = B_ * L_ * HROW;
    if (id >= MAIN + 4096) return;
    if (id >= MAIN) { g_hb[id] = 0u; return; }
    int bl = id / HROW, t = id - bl * HROW;
    float v0 = 0.f, v1 = 0.f;
    if (t < 64) {
        int tok = x[bl];
        const float* e = emb + (size_t)tok * 128 + 2 * t;
        v0 = e[0]; v1 = e[1];
    } else if (t == 64) {
        v0 = pe[bl * 2]; v1 = pe[bl * 2 + 1];
    }
    g_hb[id] = packbf(v0, v1);
}

// ---------------------------------------------------------------------------
// 2) conv1: C[n][w] = window(h)[n][704] @ w1[w][704]^T, per-batch. (R10)
// ---------------------------------------------------------------------------
__global__ __launch_bounds__(256, 2) void conv1_tc(
    const float* __restrict__ bias,
    const float* __restrict__ bg, const float* __restrict__ bb,
    const float* __restrict__ bmu, const float* __restrict__ bvv,
    const float* __restrict__ pw)
{
    extern __shared__ uint32_t sm[];
    uint32_t sb = cvta_s(sm);
    int b  = blockIdx.z;
    int m0 = blockIdx.y * 128;     // n-position tile
    int n0 = blockIdx.x * 128;     // w tile
    int t = threadIdx.x, lane = t & 31, wid = t >> 5;
    int wm = wid >> 2, wn = wid & 3;
    int fr = lane >> 2, fc = lane & 3;

    float acc[4][4][4];
    #pragma unroll
    for (int i = 0; i < 4; i++)
        #pragma unroll
        for (int j = 0; j < 4; j++)
            #pragma unroll
            for (int q = 0; q < 4; q++) acc[i][j][q] = 0.f;

    int lr = t >> 1, lc = (t & 1) * 8;
    const uint32_t* agp = g_hb + (size_t)(b * 512 + m0 + lr) * HROW + lc;
    const uint32_t* wgp = g_w1h + (size_t)(n0 + lr) * K1PW + lc;
    uint32_t aS = sb + lr * 80 + lc * 4;
    uint32_t wS = sb + 30720 + lr * 80 + lc * 4;

    uint32_t aAddr[4];
    #pragma unroll
    for (int i = 0; i < 4; i++) {
        int row = wm * 64 + 16 * i + (lane & 15);
        int col = (lane & 16) ? 4 : 0;
        aAddr[i] = sb + row * 80 + col * 4;
    }
    uint32_t bAddr = sb + 30720 + (wn * 32 + lane) * 80;

    #define C1_ISSUE(it_) do { \
        uint32_t so_ = ((it_) % 3) * 10240; \
        cp16(aS + so_, agp + (it_) * 16); \
        cp16(aS + so_ + 16, agp + (it_) * 16 + 4); \
        cp16(wS + so_, wgp + (it_) * 16); \
        cp16(wS + so_ + 16, wgp + (it_) * 16 + 4); \
    } while (0)

    C1_ISSUE(0); CP_COMMIT();
    C1_ISSUE(1); CP_COMMIT();

    for (int it = 0; it < C1_NIT; it++) {
        if (it < C1_NIT - 1) CP_WAIT1(); else CP_WAIT0();
        __syncthreads();
        uint32_t so = (it % 3) * 10240;
        #pragma unroll
        for (int ss = 0; ss < 2; ss++) {
            uint32_t ko = so + ss * 32;
            uint32_t af[4][4], b0q[4], b1q[4];
            #pragma unroll
            for (int i = 0; i < 4; i++) ldm4(af[i], aAddr[i] + ko);
            ldm4(b0q, bAddr + ko);
            ldm4(b1q, bAddr + ko + 16);
            #pragma unroll
            for (int i = 0; i < 4; i++)
                #pragma unroll
                for (int j = 0; j < 4; j++)
                    mma16(acc[i][j], af[i], b0q[j], b1q[j]);
        }
        if (it + 2 < C1_NIT) { C1_ISSUE(it + 2); CP_COMMIT(); }
    }

    float p = pw[0];
    #pragma unroll
    for (int j = 0; j < 4; j++) {
        int c = n0 + wn * 32 + 8 * j + 2 * fc;
        float s0 = rsqrtf(bvv[c] + EPSF) * bg[c];
        float o0 = bb[c] - bmu[c] * s0 + bias[c] * s0;
        float s1 = rsqrtf(bvv[c + 1] + EPSF) * bg[c + 1];
        float o1 = bb[c + 1] - bmu[c + 1] * s1 + bias[c + 1] * s1;
        #pragma unroll
        for (int i = 0; i < 4; i++) {
            int r0 = m0 + wm * 64 + 16 * i + fr;
            int r1 = r0 + 8;
            if (r0 < Lp_) {
                size_t nb = (size_t)b * Lp_ + r0;
                float v0 = acc[i][j][0] * s0 + o0;
                float v1 = acc[i][j][1] * s1 + o1;
                v0 = v0 > 0.f ? v0 : p * v0;
                v1 = v1 > 0.f ? v1 : p * v1;
                uint32_t pk = packbf(v0, v1);
                g_yh[nb * 128 + (c >> 1)]  = pk;
                g_xIh[nb * 128 + (c >> 1)] = pk;
            }
            if (r1 < Lp_) {
                size_t nb = (size_t)b * Lp_ + r1;
                float v2 = acc[i][j][2] * s0 + o0;
                float v3 = acc[i][j][3] * s1 + o1;
                v2 = v2 > 0.f ? v2 : p * v2;
                v3 = v3 > 0.f ? v3 : p * v3;
                uint32_t pk = packbf(v2, v3);
                g_yh[nb * 128 + (c >> 1)]  = pk;
                g_xIh[nb * 128 + (c >> 1)] = pk;
            }
        }
    }
}

// ---------------------------------------------------------------------------
// 3) cb GEMM: weight-resident multi-tile; k16 stages, 4-stage A ring. (R10)
// ---------------------------------------------------------------------------
__global__ __launch_bounds__(256, 2) void cb_tc2(int blk, const float* __restrict__ bias)
{
    extern __shared__ uint32_t sm4[];
    __shared__ float sred[8];
    uint32_t sb = cvta_s(sm4);
    const uint32_t A0 = sb;                 // 4 stages * 6144 B
    const uint32_t W0 = sb + 24576;         // 128 rows * 528 B
    int n0 = blockIdx.x * 128;
    int tgrp = blockIdx.y;                  // 0..126, tiles tgrp*4 .. +3
    int t = threadIdx.x, lane = t & 31, wid = t >> 5;
    int wm = wid >> 2, wn = wid & 3;
    int fr = lane >> 2, fc = lane & 3;
    if (t < 8) sred[t] = 0.f;

    {
        const char* wbase = (const char*)g_cbwh + (size_t)(blk * 256 + n0) * 512;
        #pragma unroll
        for (int i = 0; i < 16; i++) {
            int c = t + 256 * i;
            int row = c >> 5, col = c & 31;
            cp16(W0 + row * 528 + col * 16, wbase + row * 512 + col * 16);
        }
    }

    int arow = t >> 1, ahalf = t & 1;
    const char* abase = (const char*)g_yh +
        ((size_t)(tgrp * 4) * 128 + arow) * 512 + ahalf * 16;
    uint32_t aS = A0 + arow * 48 + ahalf * 16;

    #define CB2_ISSUE(s_) \
        cp16(aS + ((s_) & 3) * 6144, \
             abase + (size_t)((s_) >> 4) * 65536 + ((s_) & 15) * 32)

    CB2_ISSUE(0); CP_COMMIT();
    CB2_ISSUE(1); CP_COMMIT();
    CB2_ISSUE(2); CP_COMMIT();

    uint32_t aAddr[4];
    #pragma unroll
    for (int i = 0; i < 4; i++)
        aAddr[i] = A0 + (wm * 64 + 16 * i + (lane & 15)) * 48 + ((lane & 16) ? 16 : 0);
    uint32_t bAddr = W0 + (wn * 32 + lane) * 528;

    float acc[4][4][4];
    float* psl = g_psum2 + blk * B_ * G_ * 2;

    for (int s = 0; s < CB_NIT; s++) {
        if ((s & 15) == 0) {
            #pragma unroll
            for (int i = 0; i < 4; i++)
                #pragma unroll
                for (int j = 0; j < 4; j++)
                    #pragma unroll
                    for (int q = 0; q < 4; q++) acc[i][j][q] = 0.f;
        }
        if (s < 62) CP_WAIT2(); else if (s == 62) CP_WAIT1(); else CP_WAIT0();
        __syncthreads();
        {
            uint32_t so = (s & 3) * 6144;
            uint32_t ko = (s & 15) * 32;
            uint32_t af[4][4], b0q[4], b1q[4];
            #pragma unroll
            for (int i = 0; i < 4; i++) ldm4(af[i], aAddr[i] + so);
            ldm4(b0q, bAddr + ko);
            ldm4(b1q, bAddr + ko + 16);
            #pragma unroll
            for (int i = 0; i < 4; i++)
                #pragma unroll
                for (int j = 0; j < 4; j++)
                    mma16(acc[i][j], af[i], b0q[j], b1q[j]);
        }
        if (s + 3 < CB_NIT) { CB2_ISSUE(s + 3); CP_COMMIT(); }

        if ((s & 15) == 15) {
            int tile = tgrp * 4 + (s >> 4);
            int m0 = tile * 128;
            float rs[4][2], rq[4][2];
            #pragma unroll
            for (int i = 0; i < 4; i++) { rs[i][0] = rs[i][1] = rq[i][0] = rq[i][1] = 0.f; }
            #pragma unroll
            for (int j = 0; j < 4; j++) {
                int c = n0 + wn * 32 + 8 * j + 2 * fc;
                int cp = c >> 1;
                float bi0 = bias[c], bi1 = bias[c + 1];
                #pragma unroll
                for (int i = 0; i < 4; i++) {
                    size_t r0 = m0 + wm * 64 + 16 * i + fr;
                    size_t r1 = r0 + 8;
                    float v0 = acc[i][j][0] + bi0, v1 = acc[i][j][1] + bi1;
                    float v2 = acc[i][j][2] + bi0, v3 = acc[i][j][3] + bi1;
                    g_zh[r0 * 128 + cp] = packbf(v0, v1);
                    g_zh[r1 * 128 + cp] = packbf(v2, v3);
                    rs[i][0] += v0 + v1; rq[i][0] += v0 * v0 + v1 * v1;
                    rs[i][1] += v2 + v3; rq[i][1] += v2 * v2 + v3 * v3;
                }
            }
            int b0v = m0 / Lp_;
            int thr = (b0v + 1) * Lp_;
            float s0 = 0.f, q0 = 0.f, s1 = 0.f, q1 = 0.f;
            #pragma unroll
            for (int i = 0; i < 4; i++) {
                int r0 = m0 + wm * 64 + 16 * i + fr;
                if (r0 >= thr) { s1 += rs[i][0]; q1 += rq[i][0]; }
                else           { s0 += rs[i][0]; q0 += rq[i][0]; }
                if (r0 + 8 >= thr) { s1 += rs[i][1]; q1 += rq[i][1]; }
                else               { s0 += rs[i][1]; q0 += rq[i][1]; }
            }
            #pragma unroll
            for (int o = 16; o > 0; o >>= 1) {
                s0 += __shfl_xor_sync(0xffffffffu, s0, o);
                q0 += __shfl_xor_sync(0xffffffffu, q0, o);
                s1 += __shfl_xor_sync(0xffffffffu, s1, o);
                q1 += __shfl_xor_sync(0xffffffffu, q1, o);
            }
            int gslot = wn >> 1;
            if (lane == 0) {
                atomicAdd(&sred[gslot * 2 + 0], s0);
                atomicAdd(&sred[gslot * 2 + 1], q0);
                atomicAdd(&sred[4 + gslot * 2 + 0], s1);
                atomicAdd(&sred[4 + gslot * 2 + 1], q1);
            }
            __syncthreads();
            if (t < 8) {
                int bslot = t >> 2, gs = (t >> 1) & 1, sq = t & 1;
                int bb = b0v + bslot;
                if (bb < B_) {
                    int g = (n0 >> 6) + gs;
                    atomicAdd(&psl[(bb * G_ + g) * 2 + sq], sred[t]);
                }
                sred[t] = 0.f;
            }
            __syncthreads();
        }
    }
}

// ---------------------------------------------------------------------------
// 5) GroupNorm apply + PReLU + residual, bf16 y-chain (R10 2-channel form)
// ---------------------------------------------------------------------------
__global__ void gnapply_kernel(int blk,
                               const float* __restrict__ gamma,
                               const float* __restrict__ beta,
                               const float* __restrict__ pp)
{
    unsigned idx = blockIdx.x * 256u + threadIdx.x;
    if (idx >= (unsigned)NB_ * 128u) return;
    unsigned nb = idx >> 7, wp = idx & 127;
    unsigned w0 = wp * 2;
    unsigned b = nb / Lp_;
    float2 st = gn_stats(blk, b, w0 >> 6);
    float ga0 = gamma[w0] * st.y,     be0 = beta[w0] - st.x * ga0;
    float ga1 = gamma[w0 + 1] * st.y, be1 = beta[w0 + 1] - st.x * ga1;
    float p = pp[0];
    uint32_t zu = g_zh[(size_t)nb * 128 + wp];
    uint32_t yu = g_yh[(size_t)nb * 128 + wp];
    float v0 = bf_lo(zu) * ga0 + be0; v0 = v0 > 0.f ? v0 : p * v0;
    float v1 = bf_hi(zu) * ga1 + be1; v1 = v1 > 0.f ? v1 : p * v1;
    float y0 = bf_lo(yu) + v0;
    float y1 = bf_hi(yu) + v1;
    g_yh[(size_t)nb * 128 + wp] = packbf(y0, y1);
}

// ---------------------------------------------------------------------------
// 6a) FINAL iter partial: gnapply + residual + xI + masked max; 128 threads,
//     one bf16-PAIR per thread (each load serves both channels).
// ---------------------------------------------------------------------------
__global__ void pmax_kernel(int blk,
                            const int* __restrict__ posE,
                            const float* __restrict__ gamma,
                            const float* __restrict__ beta,
                            const float* __restrict__ pp)
{
    int b = blockIdx.x, ch = blockIdx.y, wp = threadIdx.x;   // 0..127
    int w0 = wp * 2, w1 = w0 + 1;
    int p0 = posE[b * 2] + 1;
    int p1 = posE[b * 2 + 1] + 1;
    float2 st = gn_stats(blk, b, w0 >> 6);
    float ga0 = gamma[w0] * st.y, be0 = beta[w0] - st.x * ga0;
    float ga1 = gamma[w1] * st.y, be1 = beta[w1] - st.x * ga1;
    float p = pp[0];
    float m1a = FNEG, m2a = FNEG, m3a = FNEG;
    float m1b = FNEG, m2b = FNEG, m3b = FNEG;
    int l0 = ch * 64;
    int l1 = l0 + 64 < Lp_ ? l0 + 64 : Lp_;
    const uint32_t* zp = g_zh  + (size_t)(b * Lp_ + l0) * 128 + wp;
    const uint32_t* yp = g_yh  + (size_t)(b * Lp_ + l0) * 128 + wp;
    const uint32_t* xp = g_xIh + (size_t)(b * Lp_ + l0) * 128 + wp;
    #pragma unroll 4
    for (int l = l0; l < l1; l++) {
        size_t d = (size_t)(l - l0) * 128;
        uint32_t zu = zp[d];
        uint32_t yu = yp[d];
        uint32_t xu = xp[d];
        float va = bf_lo(zu) * ga0 + be0; va = va > 0.f ? va : p * va;
        float vb = bf_hi(zu) * ga1 + be1; vb = vb > 0.f ? vb : p * vb;
        float sa = bf_lo(yu) + va + bf_lo(xu);
        float sb2 = bf_hi(yu) + vb + bf_hi(xu);
        float msk1 = (l >= p0) ? NEGF : 0.f;
        float msk2 = (l < p0 || l >= p1) ? NEGF : 0.f;
        float msk3 = (l < p1) ? NEGF : 0.f;
        m1a = fmaxf(m1a, sa + msk1);
        m2a = fmaxf(m2a, sa + msk2);
        m3a = fmaxf(m3a, sa + msk3);
        m1b = fmaxf(m1b, sb2 + msk1);
        m2b = fmaxf(m2b, sb2 + msk2);
        m3b = fmaxf(m3b, sb2 + msk3);
    }
    int base = ((b * NCH + ch) * 3) * W_;
    g_pmax[base + w0] = m1a;
    g_pmax[base + w1] = m1b;
    g_pmax[base + W_ + w0] = m2a;
    g_pmax[base + W_ + w1] = m2b;
    g_pmax[base + 2 * W_ + w0] = m3a;
    g_pmax[base + 2 * W_ + w1] = m3b;
}

// ---------------------------------------------------------------------------
// 7) dense head + softmax; fused pmax reduction preamble
// ---------------------------------------------------------------------------
__global__ void dense_kernel(
    const float* __restrict__ d0w, const float* __restrict__ d0b,
    const float* __restrict__ d1w, const float* __restrict__ d1b,
    const float* __restrict__ bndg, const float* __restrict__ bndb,
    const float* __restrict__ bndm, const float* __restrict__ bndv,
    const float* __restrict__ pd,
    const float* __restrict__ finw, const float* __restrict__ finb,
    float* __restrict__ out)
{
    __shared__ float sf[3 * W_];
    __shared__ float sh[W_];
    __shared__ float sl[LBL_];
    __shared__ float red[2];
    int b = blockIdx.x, t = threadIdx.x;

    {
        float m1 = FNEG, m2 = FNEG, m3 = FNEG;
        #pragma unroll
        for (int ch = 0; ch < NCH; ch++) {
            int base = ((b * NCH + ch) * 3) * W_ + t;
            m1 = fmaxf(m1, g_pmax[base]);
            m2 = fmaxf(m2, g_pmax[base + W_]);
            m3 = fmaxf(m3, g_pmax[base + 2 * W_]);
        }
        sf[t] = m1;
        sf[W_ + t] = m2;
        sf[2 * W_ + t] = m3;
    }
    __syncthreads();

    float acc = d0b[t];
    {
        const float* wr = d0w + t * (3 * W_);
        #pragma unroll 8
        for (int k = 0; k < 3 * W_; k++) acc += sf[k] * wr[k];
    }
    acc = (acc - bndm[t]) * rsqrtf(bndv[t] + EPSF) * bndg[t] + bndb[t];
    { float p = pd[0]; acc = acc > 0.f ? acc : p * acc; }
    sh[t] = acc;
    __syncthreads();

    float a2 = d1b[t];
    {
        const float* wr = d1w + t * W_;
        #pragma unroll 8
        for (int k = 0; k < W_; k++) a2 += sh[k] * wr[k];
    }
    a2 = (a2 - bndm[W_ + t]) * rsqrtf(bndv[W_ + t] + EPSF) * bndg[W_ + t] + bndb[W_ + t];
    { float p = pd[1]; a2 = a2 > 0.f ? a2 : p * a2; }
    __syncthreads();
    sh[t] = a2;
    __syncthreads();

    if (t < LBL_) {
        float a3 = finb[t];
        const float* wr = finw + t * W_;
        #pragma unroll 8
        for (int k = 0; k < W_; k++) a3 += sh[k] * wr[k];
        sl[t] = a3;
    }
    __syncthreads();
    if (t == 0) {
        float mx = FNEG;
        for (int i = 0; i < LBL_; i++) mx = fmaxf(mx, sl[i]);
        float s = 0.f;
        for (int i = 0; i < LBL_; i++) s += expf(sl[i] - mx);
        red[0] = mx;
        red[1] = 1.f / s;
    }
    __syncthreads();
    if (t < LBL_) out[b * LBL_ + t] = expf(sl[t] - red[0]) * red[1];
}

// ---------------------------------------------------------------------------
// launch
// ---------------------------------------------------------------------------
extern "C" void kernel_launch(void* const* d_in, const int* in_sizes, int n_in,
                              void* d_out, int out_size)
{
    const int*   x      = (const int*)d_in[0];
    const int*   posE   = (const int*)d_in[1];
    const float* pe     = (const float*)d_in[2];
    const float* emb    = (const float*)d_in[3];
    const float* c1w    = (const float*)d_in[4];
    const float* c1b    = (const float*)d_in[5];
    const float* bn1g   = (const float*)d_in[6];
    const float* bn1b   = (const float*)d_in[7];
    const float* bn1m   = (const float*)d_in[8];
    const float* bn1v   = (const float*)d_in[9];
    const float* p1w    = (const float*)d_in[10];
    const float* cbw    = (const float*)d_in[11];
    const float* cbb    = (const float*)d_in[12];
    const float* gng    = (const float*)d_in[13];
    const float* gnb    = (const float*)d_in[14];
    const float* cbp    = (const float*)d_in[15];
    const float* d0w    = (const float*)d_in[16];
    const float* d0b    = (const float*)d_in[17];
    const float* d1w    = (const float*)d_in[18];
    const float* d1b    = (const float*)d_in[19];
    const float* bndg   = (const float*)d_in[20];
    const float* bndb   = (const float*)d_in[21];
    const float* bndm   = (const float*)d_in[22];
    const float* bndv   = (const float*)d_in[23];
    const float* pd     = (const float*)d_in[24];
    const float* finw   = (const float*)d_in[25];
    const float* finb   = (const float*)d_in[26];
    float* out = (float*)d_out;

    const int GEMM_SMEM = 61440;
    const int CB2_SMEM  = 24576 + 67584;   // 92160
    cudaFuncSetAttribute(conv1_tc, cudaFuncAttributeMaxDynamicSharedMemorySize, GEMM_SMEM);
    cudaFuncSetAttribute(cb_tc2,   cudaFuncAttributeMaxDynamicSharedMemorySize, CB2_SMEM);

    prep_w1h<<<(W_ * K1PW + 255) / 256, 256>>>(c1w);
    prep_cbwh<<<(CN_ * W_ * 128 + 255) / 256, 256>>>(cbw);
    embed_h<<<(B_ * L_ * HROW + 4096 + 255) / 256, 256>>>(x, pe, emb);

    {
        dim3 grid(W_ / 128, 4, B_);   // (w-tiles, n-tiles, b)
        conv1_tc<<<grid, 256, GEMM_SMEM>>>(c1b, bn1g, bn1b, bn1m, bn1v, p1w);
    }

    for (int i = 0; i < CN_; i++) {
        dim3 gridc(2, 127);           // (w-tiles, tile-groups of 4)
        cb_tc2<<<gridc, 256, CB2_SMEM>>>(i, cbb + i * W_);
        if (i < CN_ - 1) {
            gnapply_kernel<<<(NB_ * 128 + 255) / 256, 256>>>(
                i, gng + i * W_, gnb + i * W_, cbp + i);
        } else {
            dim3 gp(B_, NCH);
            pmax_kernel<<<gp, 128>>>(i, posE, gng + i * W_, gnb + i * W_, cbp + i);
        }
    }

    dense_kernel<<<B_, 256>>>(d0w, d0b, d1w, d1b, bndg, bndb, bndm, bndv,
                              pd, finw, finb, out);

    (void)in_sizes; (void)n_in; (void)out_size;
}

// round 15
// speedup vs baseline: 1.0708x; 1.0089x over previous
#include <cuda_runtime.h>
#include <cuda_bf16.h>
#include <cstdint>

// Problem constants
#define B_   128
#define L_   512
#define W_   256
#define CN_  4
#define G_   4
#define Lp_  508            // L - KH + 1
#define NB_  65024          // B_*Lp_ = 508*128 exactly
#define LBL_ 53
#define EPSF 1e-5f
#define NEGF (-100000.0f)
#define FNEG (-3.0e38f)
#define GCNT 32512.0f       // 64 * Lp_

#define HROW 68             // b32 per l row of h (136 bf16: 130 data + 6 pad)
#define K1PW 352            // b32 k-pairs per conv1 weight row (704 bf16)
#define C1_NIT 22           // 352/16 b32 (k32 bf16 per stage)
#define CB_NIT 64           // 64 k16-steps (4 tiles x 16)
#define NCH 8               // l-chunks for partial max

// init job sizes
#define N_EMB (B_ * L_ * HROW + 4096)
#define N_W1  (W_ * K1PW)
#define N_CBW (CN_ * W_ * 128)
#define N_INIT (N_EMB + N_W1 + N_CBW)

// Scratch (static device memory -- no allocations allowed)
__device__ uint32_t g_hb[(size_t)B_ * L_ * HROW + 4096]; // bf16-pair h, [b*L+l][68]
__device__ uint32_t g_w1h[(size_t)W_ * K1PW];            // conv1 w [w][352]
__device__ uint32_t g_cbwh[(size_t)CN_ * W_ * 128];      // cb w, bf16 [i][256][128 b32]
__device__ uint32_t g_yh[(size_t)NB_ * 128];             // y bf16 pairs [nb][128 b32]
__device__ uint32_t g_xIh[(size_t)NB_ * 128];            // xI bf16 pairs [nb][128 b32]
__device__ uint32_t g_zh[(size_t)NB_ * 128];             // z bf16 pairs [nb][128 b32]
__device__ float    g_psum2[CN_ * B_ * G_ * 2];          // per-layer (sum, sumsq)
__device__ float    g_pmax[B_ * NCH * 3 * W_];

// ---------------------------------------------------------------------------
// helpers
// ---------------------------------------------------------------------------
__device__ __forceinline__ uint32_t cvta_s(const void* p) {
    return (uint32_t)__cvta_generic_to_shared(p);
}
__device__ __forceinline__ void cp16(uint32_t s, const void* g) {
    asm volatile("cp.async.cg.shared.global [%0],[%1],16;" :: "r"(s), "l"(g));
}
#define CP_COMMIT() asm volatile("cp.async.commit_group;")
#define CP_WAIT2()  asm volatile("cp.async.wait_group 2;")
#define CP_WAIT1()  asm volatile("cp.async.wait_group 1;")
#define CP_WAIT0()  asm volatile("cp.async.wait_group 0;")

__device__ __forceinline__ void ldm4(uint32_t* r, uint32_t addr) {
    asm volatile("ldmatrix.sync.aligned.m8n8.x4.shared.b16 {%0,%1,%2,%3}, [%4];"
        : "=r"(r[0]), "=r"(r[1]), "=r"(r[2]), "=r"(r[3]) : "r"(addr));
}

__device__ __forceinline__ void mma16(float* c, const uint32_t* a,
                                      uint32_t b0, uint32_t b1) {
    asm volatile(
        "mma.sync.aligned.m16n8k16.row.col.f32.bf16.bf16.f32 "
        "{%0,%1,%2,%3}, {%4,%5,%6,%7}, {%8,%9}, {%0,%1,%2,%3};"
        : "+f"(c[0]), "+f"(c[1]), "+f"(c[2]), "+f"(c[3])
        : "r"(a[0]), "r"(a[1]), "r"(a[2]), "r"(a[3]), "r"(b0), "r"(b1));
}

__device__ __forceinline__ uint32_t packbf(float lo, float hi) {
    __nv_bfloat162 t = __floats2bfloat162_rn(lo, hi);
    return *(uint32_t*)&t;
}
__device__ __forceinline__ float bf_lo(uint32_t u) {
    __nv_bfloat162 t = *(__nv_bfloat162*)&u;
    return __bfloat162float(t.x);
}
__device__ __forceinline__ float bf_hi(uint32_t u) {
    __nv_bfloat162 t = *(__nv_bfloat162*)&u;
    return __bfloat162float(t.y);
}
__device__ __forceinline__ float2 gn_stats(int blk, int b, int g) {
    const float* ps = g_psum2 + ((blk * B_ + b) * G_ + g) * 2;
    float s = __ldg(ps), q = __ldg(ps + 1);
    float mean = s / GCNT;
    float var  = q / GCNT - mean * mean;
    return make_float2(mean, rsqrtf(var + EPSF));
}

// ---------------------------------------------------------------------------
// 0) fused init: embed_h + prep_w1h + prep_cbwh + psum zero, one launch.
// ---------------------------------------------------------------------------
__global__ void init_all(const int* __restrict__ x,
                         const float* __restrict__ pe,
                         const float* __restrict__ emb,
                         const float* __restrict__ w1,
                         const float* __restrict__ cbw)
{
    int id = blockIdx.x * 256 + threadIdx.x;
    if (id < N_EMB) {
        // ---- embed ----
        const int MAIN = B_ * L_ * HROW;
        if (id >= MAIN) { g_hb[id] = 0u; return; }
        int bl = id / HROW, t = id - bl * HROW;
        float v0 = 0.f, v1 = 0.f;
        if (t < 64) {
            int tok = x[bl];
            const float* e = emb + (size_t)tok * 128 + 2 * t;
            v0 = e[0]; v1 = e[1];
        } else if (t == 64) {
            v0 = pe[bl * 2]; v1 = pe[bl * 2 + 1];
        }
        g_hb[id] = packbf(v0, v1);
        return;
    }
    id -= N_EMB;
    if (id < N_W1) {
        // ---- conv1 weight prep (window layout) ----
        int m = id / K1PW, kp = id - m * K1PW;
        int ks = 2 * kp;
        float v0 = 0.f, v1 = 0.f;
        int seg0 = ks / 136, off0 = ks - seg0 * 136;
        if (seg0 < 5 && off0 < 130) v0 = w1[m * 650 + seg0 * 130 + off0];
        int ks1 = ks + 1;
        int seg1 = ks1 / 136, off1 = ks1 - seg1 * 136;
        if (seg1 < 5 && off1 < 130) v1 = w1[m * 650 + seg1 * 130 + off1];
        g_w1h[id] = packbf(v0, v1);
        return;
    }
    id -= N_W1;
    if (id < N_CBW) {
        if (id < CN_ * B_ * G_ * 2) g_psum2[id] = 0.f;
        int row = id >> 7;
        int kp  = id & 127;
        const float* src = cbw + (size_t)row * W_ + 2 * kp;
        g_cbwh[id] = packbf(src[0], src[1]);
    }
}

// ---------------------------------------------------------------------------
// 2) conv1: C[n][w] = window(h)[n][704] @ w1[w][704]^T, per-batch. (R10)
// ---------------------------------------------------------------------------
__global__ __launch_bounds__(256, 2) void conv1_tc(
    const float* __restrict__ bias,
    const float* __restrict__ bg, const float* __restrict__ bb,
    const float* __restrict__ bmu, const float* __restrict__ bvv,
    const float* __restrict__ pw)
{
    extern __shared__ uint32_t sm[];
    uint32_t sb = cvta_s(sm);
    int b  = blockIdx.z;
    int m0 = blockIdx.y * 128;     // n-position tile
    int n0 = blockIdx.x * 128;     // w tile
    int t = threadIdx.x, lane = t & 31, wid = t >> 5;
    int wm = wid >> 2, wn = wid & 3;
    int fr = lane >> 2, fc = lane & 3;

    float acc[4][4][4];
    #pragma unroll
    for (int i = 0; i < 4; i++)
        #pragma unroll
        for (int j = 0; j < 4; j++)
            #pragma unroll
            for (int q = 0; q < 4; q++) acc[i][j][q] = 0.f;

    int lr = t >> 1, lc = (t & 1) * 8;
    const uint32_t* agp = g_hb + (size_t)(b * 512 + m0 + lr) * HROW + lc;
    const uint32_t* wgp = g_w1h + (size_t)(n0 + lr) * K1PW + lc;
    uint32_t aS = sb + lr * 80 + lc * 4;
    uint32_t wS = sb + 30720 + lr * 80 + lc * 4;

    uint32_t aAddr[4];
    #pragma unroll
    for (int i = 0; i < 4; i++) {
        int row = wm * 64 + 16 * i + (lane & 15);
        int col = (lane & 16) ? 4 : 0;
        aAddr[i] = sb + row * 80 + col * 4;
    }
    uint32_t bAddr = sb + 30720 + (wn * 32 + lane) * 80;

    #define C1_ISSUE(it_) do { \
        uint32_t so_ = ((it_) % 3) * 10240; \
        cp16(aS + so_, agp + (it_) * 16); \
        cp16(aS + so_ + 16, agp + (it_) * 16 + 4); \
        cp16(wS + so_, wgp + (it_) * 16); \
        cp16(wS + so_ + 16, wgp + (it_) * 16 + 4); \
    } while (0)

    C1_ISSUE(0); CP_COMMIT();
    C1_ISSUE(1); CP_COMMIT();

    for (int it = 0; it < C1_NIT; it++) {
        if (it < C1_NIT - 1) CP_WAIT1(); else CP_WAIT0();
        __syncthreads();
        uint32_t so = (it % 3) * 10240;
        #pragma unroll
        for (int ss = 0; ss < 2; ss++) {
            uint32_t ko = so + ss * 32;
            uint32_t af[4][4], b0q[4], b1q[4];
            #pragma unroll
            for (int i = 0; i < 4; i++) ldm4(af[i], aAddr[i] + ko);
            ldm4(b0q, bAddr + ko);
            ldm4(b1q, bAddr + ko + 16);
            #pragma unroll
            for (int i = 0; i < 4; i++)
                #pragma unroll
                for (int j = 0; j < 4; j++)
                    mma16(acc[i][j], af[i], b0q[j], b1q[j]);
        }
        if (it + 2 < C1_NIT) { C1_ISSUE(it + 2); CP_COMMIT(); }
    }

    float p = pw[0];
    #pragma unroll
    for (int j = 0; j < 4; j++) {
        int c = n0 + wn * 32 + 8 * j + 2 * fc;
        float s0 = rsqrtf(bvv[c] + EPSF) * bg[c];
        float o0 = bb[c] - bmu[c] * s0 + bias[c] * s0;
        float s1 = rsqrtf(bvv[c + 1] + EPSF) * bg[c + 1];
        float o1 = bb[c + 1] - bmu[c + 1] * s1 + bias[c + 1] * s1;
        #pragma unroll
        for (int i = 0; i < 4; i++) {
            int r0 = m0 + wm * 64 + 16 * i + fr;
            int r1 = r0 + 8;
            if (r0 < Lp_) {
                size_t nb = (size_t)b * Lp_ + r0;
                float v0 = acc[i][j][0] * s0 + o0;
                float v1 = acc[i][j][1] * s1 + o1;
                v0 = v0 > 0.f ? v0 : p * v0;
                v1 = v1 > 0.f ? v1 : p * v1;
                uint32_t pk = packbf(v0, v1);
                g_yh[nb * 128 + (c >> 1)]  = pk;
                g_xIh[nb * 128 + (c >> 1)] = pk;
            }
            if (r1 < Lp_) {
                size_t nb = (size_t)b * Lp_ + r1;
                float v2 = acc[i][j][2] * s0 + o0;
                float v3 = acc[i][j][3] * s1 + o1;
                v2 = v2 > 0.f ? v2 : p * v2;
                v3 = v3 > 0.f ? v3 : p * v3;
                uint32_t pk = packbf(v2, v3);
                g_yh[nb * 128 + (c >> 1)]  = pk;
                g_xIh[nb * 128 + (c >> 1)] = pk;
            }
        }
    }
}

// ---------------------------------------------------------------------------
// 3) cb GEMM: weight-resident multi-tile; k16 stages, 4-stage A ring. (R10)
// ---------------------------------------------------------------------------
__global__ __launch_bounds__(256, 2) void cb_tc2(int blk, const float* __restrict__ bias)
{
    extern __shared__ uint32_t sm4[];
    __shared__ float sred[8];
    uint32_t sb = cvta_s(sm4);
    const uint32_t A0 = sb;                 // 4 stages * 6144 B
    const uint32_t W0 = sb + 24576;         // 128 rows * 528 B
    int n0 = blockIdx.x * 128;
    int tgrp = blockIdx.y;                  // 0..126, tiles tgrp*4 .. +3
    int t = threadIdx.x, lane = t & 31, wid = t >> 5;
    int wm = wid >> 2, wn = wid & 3;
    int fr = lane >> 2, fc = lane & 3;
    if (t < 8) sred[t] = 0.f;

    {
        const char* wbase = (const char*)g_cbwh + (size_t)(blk * 256 + n0) * 512;
        #pragma unroll
        for (int i = 0; i < 16; i++) {
            int c = t + 256 * i;
            int row = c >> 5, col = c & 31;
            cp16(W0 + row * 528 + col * 16, wbase + row * 512 + col * 16);
        }
    }

    int arow = t >> 1, ahalf = t & 1;
    const char* abase = (const char*)g_yh +
        ((size_t)(tgrp * 4) * 128 + arow) * 512 + ahalf * 16;
    uint32_t aS = A0 + arow * 48 + ahalf * 16;

    #define CB2_ISSUE(s_) \
        cp16(aS + ((s_) & 3) * 6144, \
             abase + (size_t)((s_) >> 4) * 65536 + ((s_) & 15) * 32)

    CB2_ISSUE(0); CP_COMMIT();
    CB2_ISSUE(1); CP_COMMIT();
    CB2_ISSUE(2); CP_COMMIT();

    uint32_t aAddr[4];
    #pragma unroll
    for (int i = 0; i < 4; i++)
        aAddr[i] = A0 + (wm * 64 + 16 * i + (lane & 15)) * 48 + ((lane & 16) ? 16 : 0);
    uint32_t bAddr = W0 + (wn * 32 + lane) * 528;

    float acc[4][4][4];
    float* psl = g_psum2 + blk * B_ * G_ * 2;

    for (int s = 0; s < CB_NIT; s++) {
        if ((s & 15) == 0) {
            #pragma unroll
            for (int i = 0; i < 4; i++)
                #pragma unroll
                for (int j = 0; j < 4; j++)
                    #pragma unroll
                    for (int q = 0; q < 4; q++) acc[i][j][q] = 0.f;
        }
        if (s < 62) CP_WAIT2(); else if (s == 62) CP_WAIT1(); else CP_WAIT0();
        __syncthreads();
        {
            uint32_t so = (s & 3) * 6144;
            uint32_t ko = (s & 15) * 32;
            uint32_t af[4][4], b0q[4], b1q[4];
            #pragma unroll
            for (int i = 0; i < 4; i++) ldm4(af[i], aAddr[i] + so);
            ldm4(b0q, bAddr + ko);
            ldm4(b1q, bAddr + ko + 16);
            #pragma unroll
            for (int i = 0; i < 4; i++)
                #pragma unroll
                for (int j = 0; j < 4; j++)
                    mma16(acc[i][j], af[i], b0q[j], b1q[j]);
        }
        if (s + 3 < CB_NIT) { CB2_ISSUE(s + 3); CP_COMMIT(); }

        if ((s & 15) == 15) {
            int tile = tgrp * 4 + (s >> 4);
            int m0 = tile * 128;
            float rs[4][2], rq[4][2];
            #pragma unroll
            for (int i = 0; i < 4; i++) { rs[i][0] = rs[i][1] = rq[i][0] = rq[i][1] = 0.f; }
            #pragma unroll
            for (int j = 0; j < 4; j++) {
                int c = n0 + wn * 32 + 8 * j + 2 * fc;
                int cp = c >> 1;
                float bi0 = bias[c], bi1 = bias[c + 1];
                #pragma unroll
                for (int i = 0; i < 4; i++) {
                    size_t r0 = m0 + wm * 64 + 16 * i + fr;
                    size_t r1 = r0 + 8;
                    float v0 = acc[i][j][0] + bi0, v1 = acc[i][j][1] + bi1;
                    float v2 = acc[i][j][2] + bi0, v3 = acc[i][j][3] + bi1;
                    g_zh[r0 * 128 + cp] = packbf(v0, v1);
                    g_zh[r1 * 128 + cp] = packbf(v2, v3);
                    rs[i][0] += v0 + v1; rq[i][0] += v0 * v0 + v1 * v1;
                    rs[i][1] += v2 + v3; rq[i][1] += v2 * v2 + v3 * v3;
                }
            }
            int b0v = m0 / Lp_;
            int thr = (b0v + 1) * Lp_;
            float s0 = 0.f, q0 = 0.f, s1 = 0.f, q1 = 0.f;
            #pragma unroll
            for (int i = 0; i < 4; i++) {
                int r0 = m0 + wm * 64 + 16 * i + fr;
                if (r0 >= thr) { s1 += rs[i][0]; q1 += rq[i][0]; }
                else           { s0 += rs[i][0]; q0 += rq[i][0]; }
                if (r0 + 8 >= thr) { s1 += rs[i][1]; q1 += rq[i][1]; }
                else               { s0 += rs[i][1]; q0 += rq[i][1]; }
            }
            #pragma unroll
            for (int o = 16; o > 0; o >>= 1) {
                s0 += __shfl_xor_sync(0xffffffffu, s0, o);
                q0 += __shfl_xor_sync(0xffffffffu, q0, o);
                s1 += __shfl_xor_sync(0xffffffffu, s1, o);
                q1 += __shfl_xor_sync(0xffffffffu, q1, o);
            }
            int gslot = wn >> 1;
            if (lane == 0) {
                atomicAdd(&sred[gslot * 2 + 0], s0);
                atomicAdd(&sred[gslot * 2 + 1], q0);
                atomicAdd(&sred[4 + gslot * 2 + 0], s1);
                atomicAdd(&sred[4 + gslot * 2 + 1], q1);
            }
            __syncthreads();
            if (t < 8) {
                int bslot = t >> 2, gs = (t >> 1) & 1, sq = t & 1;
                int bb = b0v + bslot;
                if (bb < B_) {
                    int g = (n0 >> 6) + gs;
                    atomicAdd(&psl[(bb * G_ + g) * 2 + sq], sred[t]);
                }
                sred[t] = 0.f;
            }
            __syncthreads();
        }
    }
}

// ---------------------------------------------------------------------------
// 5) GroupNorm apply + PReLU + residual, bf16 y-chain (R10 2-channel form)
// ---------------------------------------------------------------------------
__global__ void gnapply_kernel(int blk,
                               const float* __restrict__ gamma,
                               const float* __restrict__ beta,
                               const float* __restrict__ pp)
{
    unsigned idx = blockIdx.x * 256u + threadIdx.x;
    if (idx >= (unsigned)NB_ * 128u) return;
    unsigned nb = idx >> 7, wp = idx & 127;
    unsigned w0 = wp * 2;
    unsigned b = nb / Lp_;
    float2 st = gn_stats(blk, b, w0 >> 6);
    float ga0 = gamma[w0] * st.y,     be0 = beta[w0] - st.x * ga0;
    float ga1 = gamma[w0 + 1] * st.y, be1 = beta[w0 + 1] - st.x * ga1;
    float p = pp[0];
    uint32_t zu = g_zh[(size_t)nb * 128 + wp];
    uint32_t yu = g_yh[(size_t)nb * 128 + wp];
    float v0 = bf_lo(zu) * ga0 + be0; v0 = v0 > 0.f ? v0 : p * v0;
    float v1 = bf_hi(zu) * ga1 + be1; v1 = v1 > 0.f ? v1 : p * v1;
    float y0 = bf_lo(yu) + v0;
    float y1 = bf_hi(yu) + v1;
    g_yh[(size_t)nb * 128 + wp] = packbf(y0, y1);
}

// ---------------------------------------------------------------------------
// 6a) FINAL iter partial: one bf16-pair per thread (R14 form)
// ---------------------------------------------------------------------------
__global__ void pmax_kernel(int blk,
                            const int* __restrict__ posE,
                            const float* __restrict__ gamma,
                            const float* __restrict__ beta,
                            const float* __restrict__ pp)
{
    int b = blockIdx.x, ch = blockIdx.y, wp = threadIdx.x;   // 0..127
    int w0 = wp * 2, w1 = w0 + 1;
    int p0 = posE[b * 2] + 1;
    int p1 = posE[b * 2 + 1] + 1;
    float2 st = gn_stats(blk, b, w0 >> 6);
    float ga0 = gamma[w0] * st.y, be0 = beta[w0] - st.x * ga0;
    float ga1 = gamma[w1] * st.y, be1 = beta[w1] - st.x * ga1;
    float p = pp[0];
    float m1a = FNEG, m2a = FNEG, m3a = FNEG;
    float m1b = FNEG, m2b = FNEG, m3b = FNEG;
    int l0 = ch * 64;
    int l1 = l0 + 64 < Lp_ ? l0 + 64 : Lp_;
    const uint32_t* zp = g_zh  + (size_t)(b * Lp_ + l0) * 128 + wp;
    const uint32_t* yp = g_yh  + (size_t)(b * Lp_ + l0) * 128 + wp;
    const uint32_t* xp = g_xIh + (size_t)(b * Lp_ + l0) * 128 + wp;
    #pragma unroll 4
    for (int l = l0; l < l1; l++) {
        size_t d = (size_t)(l - l0) * 128;
        uint32_t zu = zp[d];
        uint32_t yu = yp[d];
        uint32_t xu = xp[d];
        float va = bf_lo(zu) * ga0 + be0; va = va > 0.f ? va : p * va;
        float vb = bf_hi(zu) * ga1 + be1; vb = vb > 0.f ? vb : p * vb;
        float sa = bf_lo(yu) + va + bf_lo(xu);
        float sb2 = bf_hi(yu) + vb + bf_hi(xu);
        float msk1 = (l >= p0) ? NEGF : 0.f;
        float msk2 = (l < p0 || l >= p1) ? NEGF : 0.f;
        float msk3 = (l < p1) ? NEGF : 0.f;
        m1a = fmaxf(m1a, sa + msk1);
        m2a = fmaxf(m2a, sa + msk2);
        m3a = fmaxf(m3a, sa + msk3);
        m1b = fmaxf(m1b, sb2 + msk1);
        m2b = fmaxf(m2b, sb2 + msk2);
        m3b = fmaxf(m3b, sb2 + msk3);
    }
    int base = ((b * NCH + ch) * 3) * W_;
    g_pmax[base + w0] = m1a;
    g_pmax[base + w1] = m1b;
    g_pmax[base + W_ + w0] = m2a;
    g_pmax[base + W_ + w1] = m2b;
    g_pmax[base + 2 * W_ + w0] = m3a;
    g_pmax[base + 2 * W_ + w1] = m3b;
}

// ---------------------------------------------------------------------------
// 7) dense head + softmax; fused pmax reduction preamble
// ---------------------------------------------------------------------------
__global__ void dense_kernel(
    const float* __restrict__ d0w, const float* __restrict__ d0b,
    const float* __restrict__ d1w, const float* __restrict__ d1b,
    const float* __restrict__ bndg, const float* __restrict__ bndb,
    const float* __restrict__ bndm, const float* __restrict__ bndv,
    const float* __restrict__ pd,
    const float* __restrict__ finw, const float* __restrict__ finb,
    float* __restrict__ out)
{
    __shared__ float sf[3 * W_];
    __shared__ float sh[W_];
    __shared__ float sl[LBL_];
    __shared__ float red[2];
    int b = blockIdx.x, t = threadIdx.x;

    {
        float m1 = FNEG, m2 = FNEG, m3 = FNEG;
        #pragma unroll
        for (int ch = 0; ch < NCH; ch++) {
            int base = ((b * NCH + ch) * 3) * W_ + t;
            m1 = fmaxf(m1, g_pmax[base]);
            m2 = fmaxf(m2, g_pmax[base + W_]);
            m3 = fmaxf(m3, g_pmax[base + 2 * W_]);
        }
        sf[t] = m1;
        sf[W_ + t] = m2;
        sf[2 * W_ + t] = m3;
    }
    __syncthreads();

    float acc = d0b[t];
    {
        const float* wr = d0w + t * (3 * W_);
        #pragma unroll 8
        for (int k = 0; k < 3 * W_; k++) acc += sf[k] * wr[k];
    }
    acc = (acc - bndm[t]) * rsqrtf(bndv[t] + EPSF) * bndg[t] + bndb[t];
    { float p = pd[0]; acc = acc > 0.f ? acc : p * acc; }
    sh[t] = acc;
    __syncthreads();

    float a2 = d1b[t];
    {
        const float* wr = d1w + t * W_;
        #pragma unroll 8
        for (int k = 0; k < W_; k++) a2 += sh[k] * wr[k];
    }
    a2 = (a2 - bndm[W_ + t]) * rsqrtf(bndv[W_ + t] + EPSF) * bndg[W_ + t] + bndb[W_ + t];
    { float p = pd[1]; a2 = a2 > 0.f ? a2 : p * a2; }
    __syncthreads();
    sh[t] = a2;
    __syncthreads();

    if (t < LBL_) {
        float a3 = finb[t];
        const float* wr = finw + t * W_;
        #pragma unroll 8
        for (int k = 0; k < W_; k++) a3 += sh[k] * wr[k];
        sl[t] = a3;
    }
    __syncthreads();
    if (t == 0) {
        float mx = FNEG;
        for (int i = 0; i < LBL_; i++) mx = fmaxf(mx, sl[i]);
        float s = 0.f;
        for (int i = 0; i < LBL_; i++) s += expf(sl[i] - mx);
        red[0] = mx;
        red[1] = 1.f / s;
    }
    __syncthreads();
    if (t < LBL_) out[b * LBL_ + t] = expf(sl[t] - red[0]) * red[1];
}

// ---------------------------------------------------------------------------
// launch
// ---------------------------------------------------------------------------
extern "C" void kernel_launch(void* const* d_in, const int* in_sizes, int n_in,
                              void* d_out, int out_size)
{
    const int*   x      = (const int*)d_in[0];
    const int*   posE   = (const int*)d_in[1];
    const float* pe     = (const float*)d_in[2];
    const float* emb    = (const float*)d_in[3];
    const float* c1w    = (const float*)d_in[4];
    const float* c1b    = (const float*)d_in[5];
    const float* bn1g   = (const float*)d_in[6];
    const float* bn1b   = (const float*)d_in[7];
    const float* bn1m   = (const float*)d_in[8];
    const float* bn1v   = (const float*)d_in[9];
    const float* p1w    = (const float*)d_in[10];
    const float* cbw    = (const float*)d_in[11];
    const float* cbb    = (const float*)d_in[12];
    const float* gng    = (const float*)d_in[13];
    const float* gnb    = (const float*)d_in[14];
    const float* cbp    = (const float*)d_in[15];
    const float* d0w    = (const float*)d_in[16];
    const float* d0b    = (const float*)d_in[17];
    const float* d1w    = (const float*)d_in[18];
    const float* d1b    = (const float*)d_in[19];
    const float* bndg   = (const float*)d_in[20];
    const float* bndb   = (const float*)d_in[21];
    const float* bndm   = (const float*)d_in[22];
    const float* bndv   = (const float*)d_in[23];
    const float* pd     = (const float*)d_in[24];
    const float* finw   = (const float*)d_in[25];
    const float* finb   = (const float*)d_in[26];
    float* out = (float*)d_out;

    const int GEMM_SMEM = 61440;
    const int CB2_SMEM  = 24576 + 67584;   // 92160
    cudaFuncSetAttribute(conv1_tc, cudaFuncAttributeMaxDynamicSharedMemorySize, GEMM_SMEM);
    cudaFuncSetAttribute(cb_tc2,   cudaFuncAttributeMaxDynamicSharedMemorySize, CB2_SMEM);

    init_all<<<(N_INIT + 255) / 256, 256>>>(x, pe, emb, c1w, cbw);

    {
        dim3 grid(W_ / 128, 4, B_);   // (w-tiles, n-tiles, b)
        conv1_tc<<<grid, 256, GEMM_SMEM>>>(c1b, bn1g, bn1b, bn1m, bn1v, p1w);
    }

    for (int i = 0; i < CN_; i++) {
        dim3 gridc(2, 127);           // (w-tiles, tile-groups of 4)
        cb_tc2<<<gridc, 256, CB2_SMEM>>>(i, cbb + i * W_);
        if (i < CN_ - 1) {
            gnapply_kernel<<<(NB_ * 128 + 255) / 256, 256>>>(
                i, gng + i * W_, gnb + i * W_, cbp + i);
        } else {
            dim3 gp(B_, NCH);
            pmax_kernel<<<gp, 128>>>(i, posE, gng + i * W_, gnb + i * W_, cbp + i);
        }
    }

    dense_kernel<<<B_, 256>>>(d0w, d0b, d1w, d1b, bndg, bndb, bndm, bndv,
                              pd, finw, finb, out);

    (void)in_sizes; (void)n_in; (void)out_size;
}

// round 16
// speedup vs baseline: 1.1453x; 1.0695x over previous
#include <cuda_runtime.h>
#include <cuda_bf16.h>
#include <cstdint>

// Problem constants
#define B_   128
#define L_   512
#define W_   256
#define CN_  4
#define G_   4
#define Lp_  508            // L - KH + 1
#define NB_  65024          // B_*Lp_ = 508*128 exactly
#define LBL_ 53
#define EPSF 1e-5f
#define NEGF (-100000.0f)
#define FNEG (-3.0e38f)
#define GCNT 32512.0f       // 64 * Lp_

#define HROW 68             // b32 per l row of h (136 bf16: 130 data + 6 pad)
#define K1PW 352            // b32 k-pairs per conv1 weight row (704 bf16)
#define C1_NIT 22           // 352/16 b32 (k32 bf16 per stage)
#define CB_NIT 64           // 64 k16-steps (4 tiles x 16)
#define NCH 8               // l-chunks for partial max

// init job sizes
#define N_EMB (B_ * L_ * HROW + 4096)
#define N_W1  (W_ * K1PW)
#define N_CBW (CN_ * W_ * 128)
#define N_INIT (N_EMB + N_W1 + N_CBW)

// Scratch (static device memory -- no allocations allowed)
__device__ uint32_t g_hb[(size_t)B_ * L_ * HROW + 4096]; // bf16-pair h, [b*L+l][68]
__device__ uint32_t g_w1h[(size_t)W_ * K1PW];            // conv1 w [w][352]
__device__ uint32_t g_cbwh[(size_t)CN_ * W_ * 128];      // cb w, bf16 [i][256][128 b32]
__device__ uint32_t g_yh[(size_t)NB_ * 128];             // y bf16 pairs [nb][128 b32]
__device__ uint32_t g_xIh[(size_t)NB_ * 128];            // xI bf16 pairs [nb][128 b32]
__device__ uint32_t g_zh[(size_t)NB_ * 128];             // z bf16 pairs [nb][128 b32]
__device__ float    g_psum2[CN_ * B_ * G_ * 2];          // per-layer (sum, sumsq)
__device__ float    g_pmax[B_ * NCH * 3 * W_];

// ---------------------------------------------------------------------------
// helpers
// ---------------------------------------------------------------------------
__device__ __forceinline__ uint32_t cvta_s(const void* p) {
    return (uint32_t)__cvta_generic_to_shared(p);
}
__device__ __forceinline__ void cp16(uint32_t s, const void* g) {
    asm volatile("cp.async.cg.shared.global [%0],[%1],16;" :: "r"(s), "l"(g));
}
#define CP_COMMIT() asm volatile("cp.async.commit_group;")
#define CP_WAIT2()  asm volatile("cp.async.wait_group 2;")
#define CP_WAIT1()  asm volatile("cp.async.wait_group 1;")
#define CP_WAIT0()  asm volatile("cp.async.wait_group 0;")

__device__ __forceinline__ void ldm4(uint32_t* r, uint32_t addr) {
    asm volatile("ldmatrix.sync.aligned.m8n8.x4.shared.b16 {%0,%1,%2,%3}, [%4];"
        : "=r"(r[0]), "=r"(r[1]), "=r"(r[2]), "=r"(r[3]) : "r"(addr));
}

__device__ __forceinline__ void mma16(float* c, const uint32_t* a,
                                      uint32_t b0, uint32_t b1) {
    asm volatile(
        "mma.sync.aligned.m16n8k16.row.col.f32.bf16.bf16.f32 "
        "{%0,%1,%2,%3}, {%4,%5,%6,%7}, {%8,%9}, {%0,%1,%2,%3};"
        : "+f"(c[0]), "+f"(c[1]), "+f"(c[2]), "+f"(c[3])
        : "r"(a[0]), "r"(a[1]), "r"(a[2]), "r"(a[3]), "r"(b0), "r"(b1));
}

__device__ __forceinline__ uint32_t packbf(float lo, float hi) {
    __nv_bfloat162 t = __floats2bfloat162_rn(lo, hi);
    return *(uint32_t*)&t;
}
__device__ __forceinline__ float bf_lo(uint32_t u) {
    __nv_bfloat162 t = *(__nv_bfloat162*)&u;
    return __bfloat162float(t.x);
}
__device__ __forceinline__ float bf_hi(uint32_t u) {
    __nv_bfloat162 t = *(__nv_bfloat162*)&u;
    return __bfloat162float(t.y);
}
__device__ __forceinline__ float2 gn_stats(int blk, int b, int g) {
    const float* ps = g_psum2 + ((blk * B_ + b) * G_ + g) * 2;
    float s = __ldg(ps), q = __ldg(ps + 1);
    float mean = s / GCNT;
    float var  = q / GCNT - mean * mean;
    return make_float2(mean, rsqrtf(var + EPSF));
}

// ---------------------------------------------------------------------------
// 0) fused init: embed_h + prep_w1h + prep_cbwh + psum zero, one launch.
// ---------------------------------------------------------------------------
__global__ void init_all(const int* __restrict__ x,
                         const float* __restrict__ pe,
                         const float* __restrict__ emb,
                         const float* __restrict__ w1,
                         const float* __restrict__ cbw)
{
    int id = blockIdx.x * 256 + threadIdx.x;
    if (id < N_EMB) {
        const int MAIN = B_ * L_ * HROW;
        if (id >= MAIN) { g_hb[id] = 0u; return; }
        int bl = id / HROW, t = id - bl * HROW;
        float v0 = 0.f, v1 = 0.f;
        if (t < 64) {
            int tok = x[bl];
            const float* e = emb + (size_t)tok * 128 + 2 * t;
            v0 = e[0]; v1 = e[1];
        } else if (t == 64) {
            v0 = pe[bl * 2]; v1 = pe[bl * 2 + 1];
        }
        g_hb[id] = packbf(v0, v1);
        return;
    }
    id -= N_EMB;
    if (id < N_W1) {
        int m = id / K1PW, kp = id - m * K1PW;
        int ks = 2 * kp;
        float v0 = 0.f, v1 = 0.f;
        int seg0 = ks / 136, off0 = ks - seg0 * 136;
        if (seg0 < 5 && off0 < 130) v0 = w1[m * 650 + seg0 * 130 + off0];
        int ks1 = ks + 1;
        int seg1 = ks1 / 136, off1 = ks1 - seg1 * 136;
        if (seg1 < 5 && off1 < 130) v1 = w1[m * 650 + seg1 * 130 + off1];
        g_w1h[id] = packbf(v0, v1);
        return;
    }
    id -= N_W1;
    if (id < N_CBW) {
        if (id < CN_ * B_ * G_ * 2) g_psum2[id] = 0.f;
        int row = id >> 7;
        int kp  = id & 127;
        const float* src = cbw + (size_t)row * W_ + 2 * kp;
        g_cbwh[id] = packbf(src[0], src[1]);
    }
}

// ---------------------------------------------------------------------------
// 2) conv1: C[n][w] = window(h)[n][704] @ w1[w][704]^T, per-batch. (R10)
// ---------------------------------------------------------------------------
__global__ __launch_bounds__(256, 2) void conv1_tc(
    const float* __restrict__ bias,
    const float* __restrict__ bg, const float* __restrict__ bb,
    const float* __restrict__ bmu, const float* __restrict__ bvv,
    const float* __restrict__ pw)
{
    extern __shared__ uint32_t sm[];
    uint32_t sb = cvta_s(sm);
    int b  = blockIdx.z;
    int m0 = blockIdx.y * 128;     // n-position tile
    int n0 = blockIdx.x * 128;     // w tile
    int t = threadIdx.x, lane = t & 31, wid = t >> 5;
    int wm = wid >> 2, wn = wid & 3;
    int fr = lane >> 2, fc = lane & 3;

    float acc[4][4][4];
    #pragma unroll
    for (int i = 0; i < 4; i++)
        #pragma unroll
        for (int j = 0; j < 4; j++)
            #pragma unroll
            for (int q = 0; q < 4; q++) acc[i][j][q] = 0.f;

    int lr = t >> 1, lc = (t & 1) * 8;
    const uint32_t* agp = g_hb + (size_t)(b * 512 + m0 + lr) * HROW + lc;
    const uint32_t* wgp = g_w1h + (size_t)(n0 + lr) * K1PW + lc;
    uint32_t aS = sb + lr * 80 + lc * 4;
    uint32_t wS = sb + 30720 + lr * 80 + lc * 4;

    uint32_t aAddr[4];
    #pragma unroll
    for (int i = 0; i < 4; i++) {
        int row = wm * 64 + 16 * i + (lane & 15);
        int col = (lane & 16) ? 4 : 0;
        aAddr[i] = sb + row * 80 + col * 4;
    }
    uint32_t bAddr = sb + 30720 + (wn * 32 + lane) * 80;

    #define C1_ISSUE(it_) do { \
        uint32_t so_ = ((it_) % 3) * 10240; \
        cp16(aS + so_, agp + (it_) * 16); \
        cp16(aS + so_ + 16, agp + (it_) * 16 + 4); \
        cp16(wS + so_, wgp + (it_) * 16); \
        cp16(wS + so_ + 16, wgp + (it_) * 16 + 4); \
    } while (0)

    C1_ISSUE(0); CP_COMMIT();
    C1_ISSUE(1); CP_COMMIT();

    for (int it = 0; it < C1_NIT; it++) {
        if (it < C1_NIT - 1) CP_WAIT1(); else CP_WAIT0();
        __syncthreads();
        uint32_t so = (it % 3) * 10240;
        #pragma unroll
        for (int ss = 0; ss < 2; ss++) {
            uint32_t ko = so + ss * 32;
            uint32_t af[4][4], b0q[4], b1q[4];
            #pragma unroll
            for (int i = 0; i < 4; i++) ldm4(af[i], aAddr[i] + ko);
            ldm4(b0q, bAddr + ko);
            ldm4(b1q, bAddr + ko + 16);
            #pragma unroll
            for (int i = 0; i < 4; i++)
                #pragma unroll
                for (int j = 0; j < 4; j++)
                    mma16(acc[i][j], af[i], b0q[j], b1q[j]);
        }
        if (it + 2 < C1_NIT) { C1_ISSUE(it + 2); CP_COMMIT(); }
    }

    float p = pw[0];
    #pragma unroll
    for (int j = 0; j < 4; j++) {
        int c = n0 + wn * 32 + 8 * j + 2 * fc;
        float s0 = rsqrtf(bvv[c] + EPSF) * bg[c];
        float o0 = bb[c] - bmu[c] * s0 + bias[c] * s0;
        float s1 = rsqrtf(bvv[c + 1] + EPSF) * bg[c + 1];
        float o1 = bb[c + 1] - bmu[c + 1] * s1 + bias[c + 1] * s1;
        #pragma unroll
        for (int i = 0; i < 4; i++) {
            int r0 = m0 + wm * 64 + 16 * i + fr;
            int r1 = r0 + 8;
            if (r0 < Lp_) {
                size_t nb = (size_t)b * Lp_ + r0;
                float v0 = acc[i][j][0] * s0 + o0;
                float v1 = acc[i][j][1] * s1 + o1;
                v0 = v0 > 0.f ? v0 : p * v0;
                v1 = v1 > 0.f ? v1 : p * v1;
                uint32_t pk = packbf(v0, v1);
                g_yh[nb * 128 + (c >> 1)]  = pk;
                g_xIh[nb * 128 + (c >> 1)] = pk;
            }
            if (r1 < Lp_) {
                size_t nb = (size_t)b * Lp_ + r1;
                float v2 = acc[i][j][2] * s0 + o0;
                float v3 = acc[i][j][3] * s1 + o1;
                v2 = v2 > 0.f ? v2 : p * v2;
                v3 = v3 > 0.f ? v3 : p * v3;
                uint32_t pk = packbf(v2, v3);
                g_yh[nb * 128 + (c >> 1)]  = pk;
                g_xIh[nb * 128 + (c >> 1)] = pk;
            }
        }
    }
}

// ---------------------------------------------------------------------------
// 3) cb GEMM: weight-resident multi-tile; k16 stages, 4-stage A ring. (R10)
// ---------------------------------------------------------------------------
__global__ __launch_bounds__(256, 2) void cb_tc2(int blk, const float* __restrict__ bias)
{
    extern __shared__ uint32_t sm4[];
    __shared__ float sred[8];
    uint32_t sb = cvta_s(sm4);
    const uint32_t A0 = sb;                 // 4 stages * 6144 B
    const uint32_t W0 = sb + 24576;         // 128 rows * 528 B
    int n0 = blockIdx.x * 128;
    int tgrp = blockIdx.y;                  // 0..126, tiles tgrp*4 .. +3
    int t = threadIdx.x, lane = t & 31, wid = t >> 5;
    int wm = wid >> 2, wn = wid & 3;
    int fr = lane >> 2, fc = lane & 3;
    if (t < 8) sred[t] = 0.f;

    {
        const char* wbase = (const char*)g_cbwh + (size_t)(blk * 256 + n0) * 512;
        #pragma unroll
        for (int i = 0; i < 16; i++) {
            int c = t + 256 * i;
            int row = c >> 5, col = c & 31;
            cp16(W0 + row * 528 + col * 16, wbase + row * 512 + col * 16);
        }
    }

    int arow = t >> 1, ahalf = t & 1;
    const char* abase = (const char*)g_yh +
        ((size_t)(tgrp * 4) * 128 + arow) * 512 + ahalf * 16;
    uint32_t aS = A0 + arow * 48 + ahalf * 16;

    #define CB2_ISSUE(s_) \
        cp16(aS + ((s_) & 3) * 6144, \
             abase + (size_t)((s_) >> 4) * 65536 + ((s_) & 15) * 32)

    CB2_ISSUE(0); CP_COMMIT();
    CB2_ISSUE(1); CP_COMMIT();
    CB2_ISSUE(2); CP_COMMIT();

    uint32_t aAddr[4];
    #pragma unroll
    for (int i = 0; i < 4; i++)
        aAddr[i] = A0 + (wm * 64 + 16 * i + (lane & 15)) * 48 + ((lane & 16) ? 16 : 0);
    uint32_t bAddr = W0 + (wn * 32 + lane) * 528;

    float acc[4][4][4];
    float* psl = g_psum2 + blk * B_ * G_ * 2;

    for (int s = 0; s < CB_NIT; s++) {
        if ((s & 15) == 0) {
            #pragma unroll
            for (int i = 0; i < 4; i++)
                #pragma unroll
                for (int j = 0; j < 4; j++)
                    #pragma unroll
                    for (int q = 0; q < 4; q++) acc[i][j][q] = 0.f;
        }
        if (s < 62) CP_WAIT2(); else if (s == 62) CP_WAIT1(); else CP_WAIT0();
        __syncthreads();
        {
            uint32_t so = (s & 3) * 6144;
            uint32_t ko = (s & 15) * 32;
            uint32_t af[4][4], b0q[4], b1q[4];
            #pragma unroll
            for (int i = 0; i < 4; i++) ldm4(af[i], aAddr[i] + so);
            ldm4(b0q, bAddr + ko);
            ldm4(b1q, bAddr + ko + 16);
            #pragma unroll
            for (int i = 0; i < 4; i++)
                #pragma unroll
                for (int j = 0; j < 4; j++)
                    mma16(acc[i][j], af[i], b0q[j], b1q[j]);
        }
        if (s + 3 < CB_NIT) { CB2_ISSUE(s + 3); CP_COMMIT(); }

        if ((s & 15) == 15) {
            int tile = tgrp * 4 + (s >> 4);
            int m0 = tile * 128;
            float rs[4][2], rq[4][2];
            #pragma unroll
            for (int i = 0; i < 4; i++) { rs[i][0] = rs[i][1] = rq[i][0] = rq[i][1] = 0.f; }
            #pragma unroll
            for (int j = 0; j < 4; j++) {
                int c = n0 + wn * 32 + 8 * j + 2 * fc;
                int cp = c >> 1;
                float bi0 = bias[c], bi1 = bias[c + 1];
                #pragma unroll
                for (int i = 0; i < 4; i++) {
                    size_t r0 = m0 + wm * 64 + 16 * i + fr;
                    size_t r1 = r0 + 8;
                    float v0 = acc[i][j][0] + bi0, v1 = acc[i][j][1] + bi1;
                    float v2 = acc[i][j][2] + bi0, v3 = acc[i][j][3] + bi1;
                    g_zh[r0 * 128 + cp] = packbf(v0, v1);
                    g_zh[r1 * 128 + cp] = packbf(v2, v3);
                    rs[i][0] += v0 + v1; rq[i][0] += v0 * v0 + v1 * v1;
                    rs[i][1] += v2 + v3; rq[i][1] += v2 * v2 + v3 * v3;
                }
            }
            int b0v = m0 / Lp_;
            int thr = (b0v + 1) * Lp_;
            float s0 = 0.f, q0 = 0.f, s1 = 0.f, q1 = 0.f;
            #pragma unroll
            for (int i = 0; i < 4; i++) {
                int r0 = m0 + wm * 64 + 16 * i + fr;
                if (r0 >= thr) { s1 += rs[i][0]; q1 += rq[i][0]; }
                else           { s0 += rs[i][0]; q0 += rq[i][0]; }
                if (r0 + 8 >= thr) { s1 += rs[i][1]; q1 += rq[i][1]; }
                else               { s0 += rs[i][1]; q0 += rq[i][1]; }
            }
            #pragma unroll
            for (int o = 16; o > 0; o >>= 1) {
                s0 += __shfl_xor_sync(0xffffffffu, s0, o);
                q0 += __shfl_xor_sync(0xffffffffu, q0, o);
                s1 += __shfl_xor_sync(0xffffffffu, s1, o);
                q1 += __shfl_xor_sync(0xffffffffu, q1, o);
            }
            int gslot = wn >> 1;
            if (lane == 0) {
                atomicAdd(&sred[gslot * 2 + 0], s0);
                atomicAdd(&sred[gslot * 2 + 1], q0);
                atomicAdd(&sred[4 + gslot * 2 + 0], s1);
                atomicAdd(&sred[4 + gslot * 2 + 1], q1);
            }
            __syncthreads();
            if (t < 8) {
                int bslot = t >> 2, gs = (t >> 1) & 1, sq = t & 1;
                int bb = b0v + bslot;
                if (bb < B_) {
                    int g = (n0 >> 6) + gs;
                    atomicAdd(&psl[(bb * G_ + g) * 2 + sq], sred[t]);
                }
                sred[t] = 0.f;
            }
            __syncthreads();
        }
    }
}

// ---------------------------------------------------------------------------
// 5) GroupNorm apply + PReLU + residual; block = (b, 64-row chunk).
//    GN coefficients hoisted to smem (one rsqrt per channel per block).
// ---------------------------------------------------------------------------
__global__ __launch_bounds__(256) void gnapply_kernel(
    int blk,
    const float* __restrict__ gamma,
    const float* __restrict__ beta,
    const float* __restrict__ pp)
{
    __shared__ float sga[256], sbe[256];
    int b = blockIdx.x;
    int chunk = blockIdx.y;
    int t = threadIdx.x;
    {
        float2 st = gn_stats(blk, b, t >> 6);
        float ga = gamma[t] * st.y;
        sga[t] = ga;
        sbe[t] = beta[t] - st.x * ga;
    }
    __syncthreads();
    float p = pp[0];
    int wp = t & 127;
    int lofs = t >> 7;                  // 0 or 1
    float ga0 = sga[wp * 2], be0 = sbe[wp * 2];
    float ga1 = sga[wp * 2 + 1], be1 = sbe[wp * 2 + 1];
    int l0 = chunk * 64;
    int l1 = l0 + 64 < Lp_ ? l0 + 64 : Lp_;
    #pragma unroll 4
    for (int l = l0 + lofs; l < l1; l += 2) {
        size_t o = (size_t)(b * Lp_ + l) * 128 + wp;
        uint32_t zu = g_zh[o];
        uint32_t yu = g_yh[o];
        float v0 = bf_lo(zu) * ga0 + be0; v0 = v0 > 0.f ? v0 : p * v0;
        float v1 = bf_hi(zu) * ga1 + be1; v1 = v1 > 0.f ? v1 : p * v1;
        g_yh[o] = packbf(bf_lo(yu) + v0, bf_hi(yu) + v1);
    }
}

// ---------------------------------------------------------------------------
// 6a) FINAL iter partial: one bf16-pair per thread (R14 form)
// ---------------------------------------------------------------------------
__global__ void pmax_kernel(int blk,
                            const int* __restrict__ posE,
                            const float* __restrict__ gamma,
                            const float* __restrict__ beta,
                            const float* __restrict__ pp)
{
    int b = blockIdx.x, ch = blockIdx.y, wp = threadIdx.x;   // 0..127
    int w0 = wp * 2, w1 = w0 + 1;
    int p0 = posE[b * 2] + 1;
    int p1 = posE[b * 2 + 1] + 1;
    float2 st = gn_stats(blk, b, w0 >> 6);
    float ga0 = gamma[w0] * st.y, be0 = beta[w0] - st.x * ga0;
    float ga1 = gamma[w1] * st.y, be1 = beta[w1] - st.x * ga1;
    float p = pp[0];
    float m1a = FNEG, m2a = FNEG, m3a = FNEG;
    float m1b = FNEG, m2b = FNEG, m3b = FNEG;
    int l0 = ch * 64;
    int l1 = l0 + 64 < Lp_ ? l0 + 64 : Lp_;
    const uint32_t* zp = g_zh  + (size_t)(b * Lp_ + l0) * 128 + wp;
    const uint32_t* yp = g_yh  + (size_t)(b * Lp_ + l0) * 128 + wp;
    const uint32_t* xp = g_xIh + (size_t)(b * Lp_ + l0) * 128 + wp;
    #pragma unroll 4
    for (int l = l0; l < l1; l++) {
        size_t d = (size_t)(l - l0) * 128;
        uint32_t zu = zp[d];
        uint32_t yu = yp[d];
        uint32_t xu = xp[d];
        float va = bf_lo(zu) * ga0 + be0; va = va > 0.f ? va : p * va;
        float vb = bf_hi(zu) * ga1 + be1; vb = vb > 0.f ? vb : p * vb;
        float sa = bf_lo(yu) + va + bf_lo(xu);
        float sb2 = bf_hi(yu) + vb + bf_hi(xu);
        float msk1 = (l >= p0) ? NEGF : 0.f;
        float msk2 = (l < p0 || l >= p1) ? NEGF : 0.f;
        float msk3 = (l < p1) ? NEGF : 0.f;
        m1a = fmaxf(m1a, sa + msk1);
        m2a = fmaxf(m2a, sa + msk2);
        m3a = fmaxf(m3a, sa + msk3);
        m1b = fmaxf(m1b, sb2 + msk1);
        m2b = fmaxf(m2b, sb2 + msk2);
        m3b = fmaxf(m3b, sb2 + msk3);
    }
    int base = ((b * NCH + ch) * 3) * W_;
    g_pmax[base + w0] = m1a;
    g_pmax[base + w1] = m1b;
    g_pmax[base + W_ + w0] = m2a;
    g_pmax[base + W_ + w1] = m2b;
    g_pmax[base + 2 * W_ + w0] = m3a;
    g_pmax[base + 2 * W_ + w1] = m3b;
}

// ---------------------------------------------------------------------------
// 7) dense head + softmax; fused pmax reduction preamble
// ---------------------------------------------------------------------------
__global__ void dense_kernel(
    const float* __restrict__ d0w, const float* __restrict__ d0b,
    const float* __restrict__ d1w, const float* __restrict__ d1b,
    const float* __restrict__ bndg, const float* __restrict__ bndb,
    const float* __restrict__ bndm, const float* __restrict__ bndv,
    const float* __restrict__ pd,
    const float* __restrict__ finw, const float* __restrict__ finb,
    float* __restrict__ out)
{
    __shared__ float sf[3 * W_];
    __shared__ float sh[W_];
    __shared__ float sl[LBL_];
    __shared__ float red[2];
    int b = blockIdx.x, t = threadIdx.x;

    {
        float m1 = FNEG, m2 = FNEG, m3 = FNEG;
        #pragma unroll
        for (int ch = 0; ch < NCH; ch++) {
            int base = ((b * NCH + ch) * 3) * W_ + t;
            m1 = fmaxf(m1, g_pmax[base]);
            m2 = fmaxf(m2, g_pmax[base + W_]);
            m3 = fmaxf(m3, g_pmax[base + 2 * W_]);
        }
        sf[t] = m1;
        sf[W_ + t] = m2;
        sf[2 * W_ + t] = m3;
    }
    __syncthreads();

    float acc = d0b[t];
    {
        const float* wr = d0w + t * (3 * W_);
        #pragma unroll 8
        for (int k = 0; k < 3 * W_; k++) acc += sf[k] * wr[k];
    }
    acc = (acc - bndm[t]) * rsqrtf(bndv[t] + EPSF) * bndg[t] + bndb[t];
    { float p = pd[0]; acc = acc > 0.f ? acc : p * acc; }
    sh[t] = acc;
    __syncthreads();

    float a2 = d1b[t];
    {
        const float* wr = d1w + t * W_;
        #pragma unroll 8
        for (int k = 0; k < W_; k++) a2 += sh[k] * wr[k];
    }
    a2 = (a2 - bndm[W_ + t]) * rsqrtf(bndv[W_ + t] + EPSF) * bndg[W_ + t] + bndb[W_ + t];
    { float p = pd[1]; a2 = a2 > 0.f ? a2 : p * a2; }
    __syncthreads();
    sh[t] = a2;
    __syncthreads();

    if (t < LBL_) {
        float a3 = finb[t];
        const float* wr = finw + t * W_;
        #pragma unroll 8
        for (int k = 0; k < W_; k++) a3 += sh[k] * wr[k];
        sl[t] = a3;
    }
    __syncthreads();
    if (t == 0) {
        float mx = FNEG;
        for (int i = 0; i < LBL_; i++) mx = fmaxf(mx, sl[i]);
        float s = 0.f;
        for (int i = 0; i < LBL_; i++) s += expf(sl[i] - mx);
        red[0] = mx;
        red[1] = 1.f / s;
    }
    __syncthreads();
    if (t < LBL_) out[b * LBL_ + t] = expf(sl[t] - red[0]) * red[1];
}

// ---------------------------------------------------------------------------
// launch
// ---------------------------------------------------------------------------
extern "C" void kernel_launch(void* const* d_in, const int* in_sizes, int n_in,
                              void* d_out, int out_size)
{
    const int*   x      = (const int*)d_in[0];
    const int*   posE   = (const int*)d_in[1];
    const float* pe     = (const float*)d_in[2];
    const float* emb    = (const float*)d_in[3];
    const float* c1w    = (const float*)d_in[4];
    const float* c1b    = (const float*)d_in[5];
    const float* bn1g   = (const float*)d_in[6];
    const float* bn1b   = (const float*)d_in[7];
    const float* bn1m   = (const float*)d_in[8];
    const float* bn1v   = (const float*)d_in[9];
    const float* p1w    = (const float*)d_in[10];
    const float* cbw    = (const float*)d_in[11];
    const float* cbb    = (const float*)d_in[12];
    const float* gng    = (const float*)d_in[13];
    const float* gnb    = (const float*)d_in[14];
    const float* cbp    = (const float*)d_in[15];
    const float* d0w    = (const float*)d_in[16];
    const float* d0b    = (const float*)d_in[17];
    const float* d1w    = (const float*)d_in[18];
    const float* d1b    = (const float*)d_in[19];
    const float* bndg   = (const float*)d_in[20];
    const float* bndb   = (const float*)d_in[21];
    const float* bndm   = (const float*)d_in[22];
    const float* bndv   = (const float*)d_in[23];
    const float* pd     = (const float*)d_in[24];
    const float* finw   = (const float*)d_in[25];
    const float* finb   = (const float*)d_in[26];
    float* out = (float*)d_out;

    const int GEMM_SMEM = 61440;
    const int CB2_SMEM  = 24576 + 67584;   // 92160
    cudaFuncSetAttribute(conv1_tc, cudaFuncAttributeMaxDynamicSharedMemorySize, GEMM_SMEM);
    cudaFuncSetAttribute(cb_tc2,   cudaFuncAttributeMaxDynamicSharedMemorySize, CB2_SMEM);

    init_all<<<(N_INIT + 255) / 256, 256>>>(x, pe, emb, c1w, cbw);

    {
        dim3 grid(W_ / 128, 4, B_);   // (w-tiles, n-tiles, b)
        conv1_tc<<<grid, 256, GEMM_SMEM>>>(c1b, bn1g, bn1b, bn1m, bn1v, p1w);
    }

    for (int i = 0; i < CN_; i++) {
        dim3 gridc(2, 127);           // (w-tiles, tile-groups of 4)
        cb_tc2<<<gridc, 256, CB2_SMEM>>>(i, cbb + i * W_);
        if (i < CN_ - 1) {
            dim3 gg(B_, NCH);
            gnapply_kernel<<<gg, 256>>>(i, gng + i * W_, gnb + i * W_, cbp + i);
        } else {
            dim3 gp(B_, NCH);
            pmax_kernel<<<gp, 128>>>(i, posE, gng + i * W_, gnb + i * W_, cbp + i);
        }
    }

    dense_kernel<<<B_, 256>>>(d0w, d0b, d1w, d1b, bndg, bndb, bndm, bndv,
                              pd, finw, finb, out);

    (void)in_sizes; (void)n_in; (void)out_size;
}

// round 17
// speedup vs baseline: 1.1701x; 1.0217x over previous
#include <cuda_runtime.h>
#include <cuda_bf16.h>
#include <cstdint>

// Problem constants
#define B_   128
#define L_   512
#define W_   256
#define CN_  4
#define G_   4
#define Lp_  508            // L - KH + 1
#define NB_  65024          // B_*Lp_ = 508*128 exactly
#define LBL_ 53
#define EPSF 1e-5f
#define NEGF (-100000.0f)
#define FNEG (-3.0e38f)
#define GCNT 32512.0f       // 64 * Lp_

#define HROW 68             // b32 per l row of h (136 bf16: 130 data + 6 pad)
#define K1PW 352            // b32 k-pairs per conv1 weight row (704 bf16)
#define C1_NIT 22           // 352/16 b32 (k32 bf16 per stage)
#define CB_NIT 64           // 64 k16-steps (4 tiles x 16)
#define NCH 8               // l-chunks for partial max

// init job sizes
#define N_EMB (B_ * L_ * HROW + 4096)
#define N_W1  (W_ * K1PW)
#define N_CBW (CN_ * W_ * 128)
#define N_INIT (N_EMB + N_W1 + N_CBW)

// Scratch (static device memory -- no allocations allowed)
__device__ uint32_t g_hb[(size_t)B_ * L_ * HROW + 4096]; // bf16-pair h, [b*L+l][68]
__device__ uint32_t g_w1h[(size_t)W_ * K1PW];            // conv1 w [w][352]
__device__ uint32_t g_cbwh[(size_t)CN_ * W_ * 128];      // cb w, bf16 [i][256][128 b32]
__device__ uint32_t g_yh[(size_t)NB_ * 128];             // y bf16 pairs [nb][128 b32]
__device__ uint32_t g_xIh[(size_t)NB_ * 128];            // xI bf16 pairs [nb][128 b32]
__device__ uint32_t g_zh[(size_t)NB_ * 128];             // z bf16 pairs [nb][128 b32]
__device__ float    g_psum2[CN_ * B_ * G_ * 2];          // per-layer (sum, sumsq)
__device__ float    g_pmax[B_ * NCH * 3 * W_];

// ---------------------------------------------------------------------------
// helpers
// ---------------------------------------------------------------------------
__device__ __forceinline__ uint32_t cvta_s(const void* p) {
    return (uint32_t)__cvta_generic_to_shared(p);
}
__device__ __forceinline__ void cp16(uint32_t s, const void* g) {
    asm volatile("cp.async.cg.shared.global [%0],[%1],16;" :: "r"(s), "l"(g));
}
#define CP_COMMIT() asm volatile("cp.async.commit_group;")
#define CP_WAIT2()  asm volatile("cp.async.wait_group 2;")
#define CP_WAIT1()  asm volatile("cp.async.wait_group 1;")
#define CP_WAIT0()  asm volatile("cp.async.wait_group 0;")

__device__ __forceinline__ void ldm4(uint32_t* r, uint32_t addr) {
    asm volatile("ldmatrix.sync.aligned.m8n8.x4.shared.b16 {%0,%1,%2,%3}, [%4];"
        : "=r"(r[0]), "=r"(r[1]), "=r"(r[2]), "=r"(r[3]) : "r"(addr));
}

__device__ __forceinline__ void mma16(float* c, const uint32_t* a,
                                      uint32_t b0, uint32_t b1) {
    asm volatile(
        "mma.sync.aligned.m16n8k16.row.col.f32.bf16.bf16.f32 "
        "{%0,%1,%2,%3}, {%4,%5,%6,%7}, {%8,%9}, {%0,%1,%2,%3};"
        : "+f"(c[0]), "+f"(c[1]), "+f"(c[2]), "+f"(c[3])
        : "r"(a[0]), "r"(a[1]), "r"(a[2]), "r"(a[3]), "r"(b0), "r"(b1));
}

__device__ __forceinline__ uint32_t packbf(float lo, float hi) {
    __nv_bfloat162 t = __floats2bfloat162_rn(lo, hi);
    return *(uint32_t*)&t;
}
__device__ __forceinline__ float bf_lo(uint32_t u) {
    __nv_bfloat162 t = *(__nv_bfloat162*)&u;
    return __bfloat162float(t.x);
}
__device__ __forceinline__ float bf_hi(uint32_t u) {
    __nv_bfloat162 t = *(__nv_bfloat162*)&u;
    return __bfloat162float(t.y);
}
__device__ __forceinline__ float2 gn_stats(int blk, int b, int g) {
    const float* ps = g_psum2 + ((blk * B_ + b) * G_ + g) * 2;
    float s = __ldg(ps), q = __ldg(ps + 1);
    float mean = s / GCNT;
    float var  = q / GCNT - mean * mean;
    return make_float2(mean, rsqrtf(var + EPSF));
}

// ---------------------------------------------------------------------------
// 0) fused init: embed_h + prep_w1h + prep_cbwh + psum zero, one launch.
// ---------------------------------------------------------------------------
__global__ void init_all(const int* __restrict__ x,
                         const float* __restrict__ pe,
                         const float* __restrict__ emb,
                         const float* __restrict__ w1,
                         const float* __restrict__ cbw)
{
    int id = blockIdx.x * 256 + threadIdx.x;
    if (id < N_EMB) {
        const int MAIN = B_ * L_ * HROW;
        if (id >= MAIN) { g_hb[id] = 0u; return; }
        int bl = id / HROW, t = id - bl * HROW;
        float v0 = 0.f, v1 = 0.f;
        if (t < 64) {
            int tok = x[bl];
            const float* e = emb + (size_t)tok * 128 + 2 * t;
            v0 = e[0]; v1 = e[1];
        } else if (t == 64) {
            v0 = pe[bl * 2]; v1 = pe[bl * 2 + 1];
        }
        g_hb[id] = packbf(v0, v1);
        return;
    }
    id -= N_EMB;
    if (id < N_W1) {
        int m = id / K1PW, kp = id - m * K1PW;
        int ks = 2 * kp;
        float v0 = 0.f, v1 = 0.f;
        int seg0 = ks / 136, off0 = ks - seg0 * 136;
        if (seg0 < 5 && off0 < 130) v0 = w1[m * 650 + seg0 * 130 + off0];
        int ks1 = ks + 1;
        int seg1 = ks1 / 136, off1 = ks1 - seg1 * 136;
        if (seg1 < 5 && off1 < 130) v1 = w1[m * 650 + seg1 * 130 + off1];
        g_w1h[id] = packbf(v0, v1);
        return;
    }
    id -= N_W1;
    if (id < N_CBW) {
        if (id < CN_ * B_ * G_ * 2) g_psum2[id] = 0.f;
        int row = id >> 7;
        int kp  = id & 127;
        const float* src = cbw + (size_t)row * W_ + 2 * kp;
        g_cbwh[id] = packbf(src[0], src[1]);
    }
}

// ---------------------------------------------------------------------------
// 2) conv1: C[n][w] = window(h)[n][704] @ w1[w][704]^T, per-batch. (R10)
// ---------------------------------------------------------------------------
__global__ __launch_bounds__(256, 2) void conv1_tc(
    const float* __restrict__ bias,
    const float* __restrict__ bg, const float* __restrict__ bb,
    const float* __restrict__ bmu, const float* __restrict__ bvv,
    const float* __restrict__ pw)
{
    extern __shared__ uint32_t sm[];
    uint32_t sb = cvta_s(sm);
    int b  = blockIdx.z;
    int m0 = blockIdx.y * 128;     // n-position tile
    int n0 = blockIdx.x * 128;     // w tile
    int t = threadIdx.x, lane = t & 31, wid = t >> 5;
    int wm = wid >> 2, wn = wid & 3;
    int fr = lane >> 2, fc = lane & 3;

    float acc[4][4][4];
    #pragma unroll
    for (int i = 0; i < 4; i++)
        #pragma unroll
        for (int j = 0; j < 4; j++)
            #pragma unroll
            for (int q = 0; q < 4; q++) acc[i][j][q] = 0.f;

    int lr = t >> 1, lc = (t & 1) * 8;
    const uint32_t* agp = g_hb + (size_t)(b * 512 + m0 + lr) * HROW + lc;
    const uint32_t* wgp = g_w1h + (size_t)(n0 + lr) * K1PW + lc;
    uint32_t aS = sb + lr * 80 + lc * 4;
    uint32_t wS = sb + 30720 + lr * 80 + lc * 4;

    uint32_t aAddr[4];
    #pragma unroll
    for (int i = 0; i < 4; i++) {
        int row = wm * 64 + 16 * i + (lane & 15);
        int col = (lane & 16) ? 4 : 0;
        aAddr[i] = sb + row * 80 + col * 4;
    }
    uint32_t bAddr = sb + 30720 + (wn * 32 + lane) * 80;

    #define C1_ISSUE(it_) do { \
        uint32_t so_ = ((it_) % 3) * 10240; \
        cp16(aS + so_, agp + (it_) * 16); \
        cp16(aS + so_ + 16, agp + (it_) * 16 + 4); \
        cp16(wS + so_, wgp + (it_) * 16); \
        cp16(wS + so_ + 16, wgp + (it_) * 16 + 4); \
    } while (0)

    C1_ISSUE(0); CP_COMMIT();
    C1_ISSUE(1); CP_COMMIT();

    for (int it = 0; it < C1_NIT; it++) {
        if (it < C1_NIT - 1) CP_WAIT1(); else CP_WAIT0();
        __syncthreads();
        uint32_t so = (it % 3) * 10240;
        #pragma unroll
        for (int ss = 0; ss < 2; ss++) {
            uint32_t ko = so + ss * 32;
            uint32_t af[4][4], b0q[4], b1q[4];
            #pragma unroll
            for (int i = 0; i < 4; i++) ldm4(af[i], aAddr[i] + ko);
            ldm4(b0q, bAddr + ko);
            ldm4(b1q, bAddr + ko + 16);
            #pragma unroll
            for (int i = 0; i < 4; i++)
                #pragma unroll
                for (int j = 0; j < 4; j++)
                    mma16(acc[i][j], af[i], b0q[j], b1q[j]);
        }
        if (it + 2 < C1_NIT) { C1_ISSUE(it + 2); CP_COMMIT(); }
    }

    float p = pw[0];
    #pragma unroll
    for (int j = 0; j < 4; j++) {
        int c = n0 + wn * 32 + 8 * j + 2 * fc;
        float s0 = rsqrtf(bvv[c] + EPSF) * bg[c];
        float o0 = bb[c] - bmu[c] * s0 + bias[c] * s0;
        float s1 = rsqrtf(bvv[c + 1] + EPSF) * bg[c + 1];
        float o1 = bb[c + 1] - bmu[c + 1] * s1 + bias[c + 1] * s1;
        #pragma unroll
        for (int i = 0; i < 4; i++) {
            int r0 = m0 + wm * 64 + 16 * i + fr;
            int r1 = r0 + 8;
            if (r0 < Lp_) {
                size_t nb = (size_t)b * Lp_ + r0;
                float v0 = acc[i][j][0] * s0 + o0;
                float v1 = acc[i][j][1] * s1 + o1;
                v0 = v0 > 0.f ? v0 : p * v0;
                v1 = v1 > 0.f ? v1 : p * v1;
                uint32_t pk = packbf(v0, v1);
                g_yh[nb * 128 + (c >> 1)]  = pk;
                g_xIh[nb * 128 + (c >> 1)] = pk;
            }
            if (r1 < Lp_) {
                size_t nb = (size_t)b * Lp_ + r1;
                float v2 = acc[i][j][2] * s0 + o0;
                float v3 = acc[i][j][3] * s1 + o1;
                v2 = v2 > 0.f ? v2 : p * v2;
                v3 = v3 > 0.f ? v3 : p * v3;
                uint32_t pk = packbf(v2, v3);
                g_yh[nb * 128 + (c >> 1)]  = pk;
                g_xIh[nb * 128 + (c >> 1)] = pk;
            }
        }
    }
}

// ---------------------------------------------------------------------------
// 3) cb GEMM: weight-resident multi-tile; k16 stages, 4-stage A ring. (R10)
// ---------------------------------------------------------------------------
__global__ __launch_bounds__(256, 2) void cb_tc2(int blk, const float* __restrict__ bias)
{
    extern __shared__ uint32_t sm4[];
    __shared__ float sred[8];
    uint32_t sb = cvta_s(sm4);
    const uint32_t A0 = sb;                 // 4 stages * 6144 B
    const uint32_t W0 = sb + 24576;         // 128 rows * 528 B
    int n0 = blockIdx.x * 128;
    int tgrp = blockIdx.y;                  // 0..126, tiles tgrp*4 .. +3
    int t = threadIdx.x, lane = t & 31, wid = t >> 5;
    int wm = wid >> 2, wn = wid & 3;
    int fr = lane >> 2, fc = lane & 3;
    if (t < 8) sred[t] = 0.f;

    {
        const char* wbase = (const char*)g_cbwh + (size_t)(blk * 256 + n0) * 512;
        #pragma unroll
        for (int i = 0; i < 16; i++) {
            int c = t + 256 * i;
            int row = c >> 5, col = c & 31;
            cp16(W0 + row * 528 + col * 16, wbase + row * 512 + col * 16);
        }
    }

    int arow = t >> 1, ahalf = t & 1;
    const char* abase = (const char*)g_yh +
        ((size_t)(tgrp * 4) * 128 + arow) * 512 + ahalf * 16;
    uint32_t aS = A0 + arow * 48 + ahalf * 16;

    #define CB2_ISSUE(s_) \
        cp16(aS + ((s_) & 3) * 6144, \
             abase + (size_t)((s_) >> 4) * 65536 + ((s_) & 15) * 32)

    CB2_ISSUE(0); CP_COMMIT();
    CB2_ISSUE(1); CP_COMMIT();
    CB2_ISSUE(2); CP_COMMIT();

    uint32_t aAddr[4];
    #pragma unroll
    for (int i = 0; i < 4; i++)
        aAddr[i] = A0 + (wm * 64 + 16 * i + (lane & 15)) * 48 + ((lane & 16) ? 16 : 0);
    uint32_t bAddr = W0 + (wn * 32 + lane) * 528;

    float acc[4][4][4];
    float* psl = g_psum2 + blk * B_ * G_ * 2;

    for (int s = 0; s < CB_NIT; s++) {
        if ((s & 15) == 0) {
            #pragma unroll
            for (int i = 0; i < 4; i++)
                #pragma unroll
                for (int j = 0; j < 4; j++)
                    #pragma unroll
                    for (int q = 0; q < 4; q++) acc[i][j][q] = 0.f;
        }
        if (s < 62) CP_WAIT2(); else if (s == 62) CP_WAIT1(); else CP_WAIT0();
        __syncthreads();
        {
            uint32_t so = (s & 3) * 6144;
            uint32_t ko = (s & 15) * 32;
            uint32_t af[4][4], b0q[4], b1q[4];
            #pragma unroll
            for (int i = 0; i < 4; i++) ldm4(af[i], aAddr[i] + so);
            ldm4(b0q, bAddr + ko);
            ldm4(b1q, bAddr + ko + 16);
            #pragma unroll
            for (int i = 0; i < 4; i++)
                #pragma unroll
                for (int j = 0; j < 4; j++)
                    mma16(acc[i][j], af[i], b0q[j], b1q[j]);
        }
        if (s + 3 < CB_NIT) { CB2_ISSUE(s + 3); CP_COMMIT(); }

        if ((s & 15) == 15) {
            int tile = tgrp * 4 + (s >> 4);
            int m0 = tile * 128;
            float rs[4][2], rq[4][2];
            #pragma unroll
            for (int i = 0; i < 4; i++) { rs[i][0] = rs[i][1] = rq[i][0] = rq[i][1] = 0.f; }
            #pragma unroll
            for (int j = 0; j < 4; j++) {
                int c = n0 + wn * 32 + 8 * j + 2 * fc;
                int cp = c >> 1;
                float bi0 = bias[c], bi1 = bias[c + 1];
                #pragma unroll
                for (int i = 0; i < 4; i++) {
                    size_t r0 = m0 + wm * 64 + 16 * i + fr;
                    size_t r1 = r0 + 8;
                    float v0 = acc[i][j][0] + bi0, v1 = acc[i][j][1] + bi1;
                    float v2 = acc[i][j][2] + bi0, v3 = acc[i][j][3] + bi1;
                    g_zh[r0 * 128 + cp] = packbf(v0, v1);
                    g_zh[r1 * 128 + cp] = packbf(v2, v3);
                    rs[i][0] += v0 + v1; rq[i][0] += v0 * v0 + v1 * v1;
                    rs[i][1] += v2 + v3; rq[i][1] += v2 * v2 + v3 * v3;
                }
            }
            int b0v = m0 / Lp_;
            int thr = (b0v + 1) * Lp_;
            float s0 = 0.f, q0 = 0.f, s1 = 0.f, q1 = 0.f;
            #pragma unroll
            for (int i = 0; i < 4; i++) {
                int r0 = m0 + wm * 64 + 16 * i + fr;
                if (r0 >= thr) { s1 += rs[i][0]; q1 += rq[i][0]; }
                else           { s0 += rs[i][0]; q0 += rq[i][0]; }
                if (r0 + 8 >= thr) { s1 += rs[i][1]; q1 += rq[i][1]; }
                else               { s0 += rs[i][1]; q0 += rq[i][1]; }
            }
            #pragma unroll
            for (int o = 16; o > 0; o >>= 1) {
                s0 += __shfl_xor_sync(0xffffffffu, s0, o);
                q0 += __shfl_xor_sync(0xffffffffu, q0, o);
                s1 += __shfl_xor_sync(0xffffffffu, s1, o);
                q1 += __shfl_xor_sync(0xffffffffu, q1, o);
            }
            int gslot = wn >> 1;
            if (lane == 0) {
                atomicAdd(&sred[gslot * 2 + 0], s0);
                atomicAdd(&sred[gslot * 2 + 1], q0);
                atomicAdd(&sred[4 + gslot * 2 + 0], s1);
                atomicAdd(&sred[4 + gslot * 2 + 1], q1);
            }
            __syncthreads();
            if (t < 8) {
                int bslot = t >> 2, gs = (t >> 1) & 1, sq = t & 1;
                int bb = b0v + bslot;
                if (bb < B_) {
                    int g = (n0 >> 6) + gs;
                    atomicAdd(&psl[(bb * G_ + g) * 2 + sq], sred[t]);
                }
                sred[t] = 0.f;
            }
            __syncthreads();
        }
    }
}

// ---------------------------------------------------------------------------
// 5) GroupNorm apply + PReLU + residual; block = (b, 64-row chunk).
//    Coefficients hoisted to smem; uint2 (8 channels) per thread.
// ---------------------------------------------------------------------------
__global__ __launch_bounds__(256) void gnapply_kernel(
    int blk,
    const float* __restrict__ gamma,
    const float* __restrict__ beta,
    const float* __restrict__ pp)
{
    __shared__ float sga[256], sbe[256];
    int b = blockIdx.x;
    int chunk = blockIdx.y;
    int t = threadIdx.x;
    {
        float2 st = gn_stats(blk, b, t >> 6);
        float ga = gamma[t] * st.y;
        sga[t] = ga;
        sbe[t] = beta[t] - st.x * ga;
    }
    __syncthreads();
    float p = pp[0];
    int wp2 = t & 63;                   // uint2 index: channels wp2*4 .. +3
    int lofs = t >> 6;                  // 0..3
    float ga[4], be[4];
    #pragma unroll
    for (int k = 0; k < 4; k++) {
        ga[k] = sga[wp2 * 4 + k];
        be[k] = sbe[wp2 * 4 + k];
    }
    int l0 = chunk * 64;
    int l1 = l0 + 64 < Lp_ ? l0 + 64 : Lp_;
    for (int l = l0 + lofs; l < l1; l += 4) {
        size_t o = ((size_t)(b * Lp_ + l) * 128 + wp2 * 2) >> 1;   // uint2 index
        uint2 z2 = ((const uint2*)g_zh)[o];
        uint2 y2 = ((const uint2*)g_yh)[o];
        float v0 = bf_lo(z2.x) * ga[0] + be[0]; v0 = v0 > 0.f ? v0 : p * v0;
        float v1 = bf_hi(z2.x) * ga[1] + be[1]; v1 = v1 > 0.f ? v1 : p * v1;
        float v2 = bf_lo(z2.y) * ga[2] + be[2]; v2 = v2 > 0.f ? v2 : p * v2;
        float v3 = bf_hi(z2.y) * ga[3] + be[3]; v3 = v3 > 0.f ? v3 : p * v3;
        uint2 r2;
        r2.x = packbf(bf_lo(y2.x) + v0, bf_hi(y2.x) + v1);
        r2.y = packbf(bf_lo(y2.y) + v2, bf_hi(y2.y) + v3);
        ((uint2*)g_yh)[o] = r2;
    }
}

// ---------------------------------------------------------------------------
// 6a) FINAL iter partial: one bf16-pair per thread (R14 form)
// ---------------------------------------------------------------------------
__global__ void pmax_kernel(int blk,
                            const int* __restrict__ posE,
                            const float* __restrict__ gamma,
                            const float* __restrict__ beta,
                            const float* __restrict__ pp)
{
    int b = blockIdx.x, ch = blockIdx.y, wp = threadIdx.x;   // 0..127
    int w0 = wp * 2, w1 = w0 + 1;
    int p0 = posE[b * 2] + 1;
    int p1 = posE[b * 2 + 1] + 1;
    float2 st = gn_stats(blk, b, w0 >> 6);
    float ga0 = gamma[w0] * st.y, be0 = beta[w0] - st.x * ga0;
    float ga1 = gamma[w1] * st.y, be1 = beta[w1] - st.x * ga1;
    float p = pp[0];
    float m1a = FNEG, m2a = FNEG, m3a = FNEG;
    float m1b = FNEG, m2b = FNEG, m3b = FNEG;
    int l0 = ch * 64;
    int l1 = l0 + 64 < Lp_ ? l0 + 64 : Lp_;
    const uint32_t* zp = g_zh  + (size_t)(b * Lp_ + l0) * 128 + wp;
    const uint32_t* yp = g_yh  + (size_t)(b * Lp_ + l0) * 128 + wp;
    const uint32_t* xp = g_xIh + (size_t)(b * Lp_ + l0) * 128 + wp;
    #pragma unroll 4
    for (int l = l0; l < l1; l++) {
        size_t d = (size_t)(l - l0) * 128;
        uint32_t zu = zp[d];
        uint32_t yu = yp[d];
        uint32_t xu = xp[d];
        float va = bf_lo(zu) * ga0 + be0; va = va > 0.f ? va : p * va;
        float vb = bf_hi(zu) * ga1 + be1; vb = vb > 0.f ? vb : p * vb;
        float sa = bf_lo(yu) + va + bf_lo(xu);
        float sb2 = bf_hi(yu) + vb + bf_hi(xu);
        float msk1 = (l >= p0) ? NEGF : 0.f;
        float msk2 = (l < p0 || l >= p1) ? NEGF : 0.f;
        float msk3 = (l < p1) ? NEGF : 0.f;
        m1a = fmaxf(m1a, sa + msk1);
        m2a = fmaxf(m2a, sa + msk2);
        m3a = fmaxf(m3a, sa + msk3);
        m1b = fmaxf(m1b, sb2 + msk1);
        m2b = fmaxf(m2b, sb2 + msk2);
        m3b = fmaxf(m3b, sb2 + msk3);
    }
    int base = ((b * NCH + ch) * 3) * W_;
    g_pmax[base + w0] = m1a;
    g_pmax[base + w1] = m1b;
    g_pmax[base + W_ + w0] = m2a;
    g_pmax[base + W_ + w1] = m2b;
    g_pmax[base + 2 * W_ + w0] = m3a;
    g_pmax[base + 2 * W_ + w1] = m3b;
}

// ---------------------------------------------------------------------------
// 7) dense head + softmax; fused pmax reduction preamble
// ---------------------------------------------------------------------------
__global__ void dense_kernel(
    const float* __restrict__ d0w, const float* __restrict__ d0b,
    const float* __restrict__ d1w, const float* __restrict__ d1b,
    const float* __restrict__ bndg, const float* __restrict__ bndb,
    const float* __restrict__ bndm, const float* __restrict__ bndv,
    const float* __restrict__ pd,
    const float* __restrict__ finw, const float* __restrict__ finb,
    float* __restrict__ out)
{
    __shared__ float sf[3 * W_];
    __shared__ float sh[W_];
    __shared__ float sl[LBL_];
    __shared__ float red[2];
    int b = blockIdx.x, t = threadIdx.x;

    {
        float m1 = FNEG, m2 = FNEG, m3 = FNEG;
        #pragma unroll
        for (int ch = 0; ch < NCH; ch++) {
            int base = ((b * NCH + ch) * 3) * W_ + t;
            m1 = fmaxf(m1, g_pmax[base]);
            m2 = fmaxf(m2, g_pmax[base + W_]);
            m3 = fmaxf(m3, g_pmax[base + 2 * W_]);
        }
        sf[t] = m1;
        sf[W_ + t] = m2;
        sf[2 * W_ + t] = m3;
    }
    __syncthreads();

    float acc = d0b[t];
    {
        const float* wr = d0w + t * (3 * W_);
        #pragma unroll 8
        for (int k = 0; k < 3 * W_; k++) acc += sf[k] * wr[k];
    }
    acc = (acc - bndm[t]) * rsqrtf(bndv[t] + EPSF) * bndg[t] + bndb[t];
    { float p = pd[0]; acc = acc > 0.f ? acc : p * acc; }
    sh[t] = acc;
    __syncthreads();

    float a2 = d1b[t];
    {
        const float* wr = d1w + t * W_;
        #pragma unroll 8
        for (int k = 0; k < W_; k++) a2 += sh[k] * wr[k];
    }
    a2 = (a2 - bndm[W_ + t]) * rsqrtf(bndv[W_ + t] + EPSF) * bndg[W_ + t] + bndb[W_ + t];
    { float p = pd[1]; a2 = a2 > 0.f ? a2 : p * a2; }
    __syncthreads();
    sh[t] = a2;
    __syncthreads();

    if (t < LBL_) {
        float a3 = finb[t];
        const float* wr = finw + t * W_;
        #pragma unroll 8
        for (int k = 0; k < W_; k++) a3 += sh[k] * wr[k];
        sl[t] = a3;
    }
    __syncthreads();
    if (t == 0) {
        float mx = FNEG;
        for (int i = 0; i < LBL_; i++) mx = fmaxf(mx, sl[i]);
        float s = 0.f;
        for (int i = 0; i < LBL_; i++) s += expf(sl[i] - mx);
        red[0] = mx;
        red[1] = 1.f / s;
    }
    __syncthreads();
    if (t < LBL_) out[b * LBL_ + t] = expf(sl[t] - red[0]) * red[1];
}

// ---------------------------------------------------------------------------
// launch
// ---------------------------------------------------------------------------
extern "C" void kernel_launch(void* const* d_in, const int* in_sizes, int n_in,
                              void* d_out, int out_size)
{
    const int*   x      = (const int*)d_in[0];
    const int*   posE   = (const int*)d_in[1];
    const float* pe     = (const float*)d_in[2];
    const float* emb    = (const float*)d_in[3];
    const float* c1w    = (const float*)d_in[4];
    const float* c1b    = (const float*)d_in[5];
    const float* bn1g   = (const float*)d_in[6];
    const float* bn1b   = (const float*)d_in[7];
    const float* bn1m   = (const float*)d_in[8];
    const float* bn1v   = (const float*)d_in[9];
    const float* p1w    = (const float*)d_in[10];
    const float* cbw    = (const float*)d_in[11];
    const float* cbb    = (const float*)d_in[12];
    const float* gng    = (const float*)d_in[13];
    const float* gnb    = (const float*)d_in[14];
    const float* cbp    = (const float*)d_in[15];
    const float* d0w    = (const float*)d_in[16];
    const float* d0b    = (const float*)d_in[17];
    const float* d1w    = (const float*)d_in[18];
    const float* d1b    = (const float*)d_in[19];
    const float* bndg   = (const float*)d_in[20];
    const float* bndb   = (const float*)d_in[21];
    const float* bndm   = (const float*)d_in[22];
    const float* bndv   = (const float*)d_in[23];
    const float* pd     = (const float*)d_in[24];
    const float* finw   = (const float*)d_in[25];
    const float* finb   = (const float*)d_in[26];
    float* out = (float*)d_out;

    const int GEMM_SMEM = 61440;
    const int CB2_SMEM  = 24576 + 67584;   // 92160
    cudaFuncSetAttribute(conv1_tc, cudaFuncAttributeMaxDynamicSharedMemorySize, GEMM_SMEM);
    cudaFuncSetAttribute(cb_tc2,   cudaFuncAttributeMaxDynamicSharedMemorySize, CB2_SMEM);

    init_all<<<(N_INIT + 255) / 256, 256>>>(x, pe, emb, c1w, cbw);

    {
        dim3 grid(W_ / 128, 4, B_);   // (w-tiles, n-tiles, b)
        conv1_tc<<<grid, 256, GEMM_SMEM>>>(c1b, bn1g, bn1b, bn1m, bn1v, p1w);
    }

    for (int i = 0; i < CN_; i++) {
        dim3 gridc(2, 127);           // (w-tiles, tile-groups of 4)
        cb_tc2<<<gridc, 256, CB2_SMEM>>>(i, cbb + i * W_);
        if (i < CN_ - 1) {
            dim3 gg(B_, NCH);
            gnapply_kernel<<<gg, 256>>>(i, gng + i * W_, gnb + i * W_, cbp + i);
        } else {
            dim3 gp(B_, NCH);
            pmax_kernel<<<gp, 128>>>(i, posE, gng + i * W_, gnb + i * W_, cbp + i);
        }
    }

    dense_kernel<<<B_, 256>>>(d0w, d0b, d1w, d1b, bndg, bndb, bndm, bndv,
                              pd, finw, finb, out);

    (void)in_sizes; (void)n_in; (void)out_size;
}